// round 1
// baseline (speedup 1.0000x reference)
#include <cuda_runtime.h>

// Problem constants (fixed for this dataset)
#define D  64
#define H  128
#define K1 192          // 3*D edge-MLP input
#define TM 64           // edges/nodes per tile
#define NTHREADS 256
#define MAXN 50000

// Scratch: per-node aggregated edge messages (segment_sum target)
__device__ float g_agg[MAXN * D];

typedef unsigned long long u64;

// ---- packed f32x2 helpers (Blackwell FFMA2: 2 fp32 FMA per instruction) ----
__device__ __forceinline__ u64 dup2(float x) {
    u64 r; asm("mov.b64 %0, {%1, %1};" : "=l"(r) : "f"(x)); return r;
}
__device__ __forceinline__ void ffma2(u64 &d, u64 a, u64 b) {
    asm("fma.rn.f32x2 %0, %1, %2, %0;" : "+l"(d) : "l"(a), "l"(b));
}
__device__ __forceinline__ float2 unpk(u64 p) {
    float lo, hi; asm("mov.b64 {%0, %1}, %2;" : "=f"(lo), "=f"(hi) : "l"(p));
    return make_float2(lo, hi);
}

// ---------------------------------------------------------------------------
__global__ void zero_agg_kernel(int n4) {
    int i = blockIdx.x * blockDim.x + threadIdx.x;
    if (i < n4) reinterpret_cast<float4*>(g_agg)[i] = make_float4(0.f, 0.f, 0.f, 0.f);
}

// ---------------------------------------------------------------------------
// Edge MLP: e = relu([ef|nf[s]|nf[r]] @ We1 + be1) @ We2 + be2
// Also scatter-adds e into g_agg[receiver].
// Persistent: weights staged into smem once per CTA.
//
// smem: sW1[192*128] | sW2[128*64] | sIn[64*196] (overlaid by sH[64*132]) | sR[64]
#define EDGE_SMEM ((K1*H + H*D + TM*196) * 4 + TM * 4)

__global__ __launch_bounds__(NTHREADS, 1)
void edge_kernel(const float* __restrict__ nodef, const float* __restrict__ edgef,
                 const float* __restrict__ We1, const float* __restrict__ be1,
                 const float* __restrict__ We2, const float* __restrict__ be2,
                 const int* __restrict__ senders, const int* __restrict__ recvs,
                 float* __restrict__ e_out, int E, int N)
{
    extern __shared__ float sm[];
    float* sW1 = sm;                 // 24576 floats
    float* sW2 = sm + K1 * H;        // 8192 floats
    float* sIn = sW2 + H * D;        // 64*196 floats (rows padded to kill bank conflicts)
    int*   sR  = (int*)(sIn + TM * 196);

    const int tid = threadIdx.x;

    // Stage weights once (persistent CTA)
    {
        float4* dw = (float4*)sW1; const float4* sw = (const float4*)We1;
        for (int i = tid; i < K1 * H / 4; i += NTHREADS) dw[i] = sw[i];
        float4* dw2 = (float4*)sW2; const float4* sw2 = (const float4*)We2;
        for (int i = tid; i < H * D / 4; i += NTHREADS) dw2[i] = sw2[i];
    }

    const int ty = tid >> 4, tx = tid & 15;
    const int e0 = ty * 4;           // 4 edges per thread
    const int c0 = tx * 8;           // 8 H-cols per thread (layer1)
    const int c2 = tx * 4;           // 4 D-cols per thread (layer2)

    float b1r[8], b2r[4];
#pragma unroll
    for (int j = 0; j < 8; j++) b1r[j] = be1[c0 + j];
#pragma unroll
    for (int j = 0; j < 4; j++) b2r[j] = be2[c2 + j];

    const int nTiles = (E + TM - 1) / TM;
    const float4* nf4 = (const float4*)nodef;
    const float4* ef4 = (const float4*)edgef;
    float4* out4 = (float4*)e_out;
    float4* agg4 = (float4*)g_agg;

    for (int tile = blockIdx.x; tile < nTiles; tile += gridDim.x) {
        const int base = tile * TM;
        __syncthreads();   // protect sIn/sH/sR reuse across iterations

        // ---- stage indices + gathered inputs: sIn[le][0:192] = [ef | nf[s] | nf[r]]
        {
            const int le = tid >> 2, q = tid & 3;   // 4 threads per row
            int ge = base + le; if (ge >= E) ge = E - 1;
            const int s = senders[ge];
            const int r = recvs[ge];
            if (q == 0) sR[le] = r;
            float4* row = (float4*)(sIn + le * 196);
            const float4* ep = ef4 + (size_t)ge * 16;
            const float4* sp = nf4 + (size_t)s * 16;
            const float4* rp = nf4 + (size_t)r * 16;
#pragma unroll
            for (int j = 0; j < 4; j++) row[q + 4 * j]      = ep[q + 4 * j];
#pragma unroll
            for (int j = 0; j < 4; j++) row[16 + q + 4 * j] = sp[q + 4 * j];
#pragma unroll
            for (int j = 0; j < 4; j++) row[32 + q + 4 * j] = rp[q + 4 * j];
        }
        __syncthreads();

        // ---- layer 1: h[64][128] = relu(in @ We1 + be1), f32x2-packed over cols
        u64 acc[4][4];
#pragma unroll
        for (int i = 0; i < 4; i++)
#pragma unroll
            for (int j = 0; j < 4; j++) acc[i][j] = 0ull;

#pragma unroll 2
        for (int k = 0; k < K1; k++) {
            const u64* wr = (const u64*)(sW1 + k * H + c0);
            const u64 w0 = wr[0], w1 = wr[1], w2 = wr[2], w3 = wr[3];
#pragma unroll
            for (int i = 0; i < 4; i++) {
                const u64 a = dup2(sIn[(e0 + i) * 196 + k]);
                ffma2(acc[i][0], a, w0); ffma2(acc[i][1], a, w1);
                ffma2(acc[i][2], a, w2); ffma2(acc[i][3], a, w3);
            }
        }
        __syncthreads();   // all sIn reads done before overlay write

        // ---- bias + relu -> sH (overlays sIn), row stride 132
        float* sH = sIn;
#pragma unroll
        for (int i = 0; i < 4; i++) {
            float* hrow = sH + (e0 + i) * 132 + c0;
#pragma unroll
            for (int j = 0; j < 4; j++) {
                const float2 v = unpk(acc[i][j]);
                hrow[2 * j]     = fmaxf(v.x + b1r[2 * j],     0.f);
                hrow[2 * j + 1] = fmaxf(v.y + b1r[2 * j + 1], 0.f);
            }
        }
        __syncthreads();

        // ---- layer 2: e[64][64] = h @ We2 + be2
        u64 acc2[4][2];
#pragma unroll
        for (int i = 0; i < 4; i++) { acc2[i][0] = 0ull; acc2[i][1] = 0ull; }

#pragma unroll 2
        for (int k = 0; k < H; k++) {
            const u64* wr = (const u64*)(sW2 + k * D + c2);
            const u64 w0 = wr[0], w1 = wr[1];
#pragma unroll
            for (int i = 0; i < 4; i++) {
                const u64 a = dup2(sH[(e0 + i) * 132 + k]);
                ffma2(acc2[i][0], a, w0); ffma2(acc2[i][1], a, w1);
            }
        }

        // ---- epilogue: write e rows + scatter-add into agg[receiver]
#pragma unroll
        for (int i = 0; i < 4; i++) {
            const int ge = base + e0 + i;
            if (ge < E) {
                const float2 p = unpk(acc2[i][0]);
                const float2 q = unpk(acc2[i][1]);
                const float4 v = make_float4(p.x + b2r[0], p.y + b2r[1],
                                             q.x + b2r[2], q.y + b2r[3]);
                out4[(size_t)ge * 16 + tx] = v;
                atomicAdd(&agg4[(size_t)sR[e0 + i] * 16 + tx], v);
            }
        }
    }
}

// ---------------------------------------------------------------------------
// Node MLP: n = relu([agg|nf] @ Wn1 + bn1) @ Wn2 + bn2
// smem: sW1[128*128] | sW2[128*64] | sIn[64*132] (overlaid by sH)
#define NODE_SMEM ((H*H + H*D + TM*132) * 4)

__global__ __launch_bounds__(NTHREADS, 1)
void node_kernel(const float* __restrict__ nodef,
                 const float* __restrict__ Wn1, const float* __restrict__ bn1,
                 const float* __restrict__ Wn2, const float* __restrict__ bn2,
                 float* __restrict__ n_out, int N)
{
    extern __shared__ float sm[];
    float* sW1 = sm;               // 16384 floats
    float* sW2 = sm + H * H;       // 8192 floats
    float* sIn = sW2 + H * D;      // 64*132 floats

    const int tid = threadIdx.x;

    // Stage weights (per block; small)
    {
        float4* dw = (float4*)sW1; const float4* sw = (const float4*)Wn1;
        for (int i = tid; i < H * H / 4; i += NTHREADS) dw[i] = sw[i];
        float4* dw2 = (float4*)sW2; const float4* sw2 = (const float4*)Wn2;
        for (int i = tid; i < H * D / 4; i += NTHREADS) dw2[i] = sw2[i];
    }

    const int ty = tid >> 4, tx = tid & 15;
    const int e0 = ty * 4;
    const int c0 = tx * 8;
    const int c2 = tx * 4;
    const int base = blockIdx.x * TM;

    float b1r[8], b2r[4];
#pragma unroll
    for (int j = 0; j < 8; j++) b1r[j] = bn1[c0 + j];
#pragma unroll
    for (int j = 0; j < 4; j++) b2r[j] = bn2[c2 + j];

    const float4* nf4  = (const float4*)nodef;
    const float4* agg4 = (const float4*)g_agg;
    float4* out4 = (float4*)n_out;

    // ---- stage node_in = [agg | nf], row stride 132 floats (33 float4)
    {
        const int le = tid >> 2, q = tid & 3;
        int g = base + le; if (g >= N) g = N - 1;
        float4* row = (float4*)(sIn + le * 132);
#pragma unroll
        for (int j = 0; j < 4; j++) row[q + 4 * j]      = agg4[(size_t)g * 16 + q + 4 * j];
#pragma unroll
        for (int j = 0; j < 4; j++) row[16 + q + 4 * j] = nf4[(size_t)g * 16 + q + 4 * j];
    }
    __syncthreads();

    // ---- layer 1
    u64 acc[4][4];
#pragma unroll
    for (int i = 0; i < 4; i++)
#pragma unroll
        for (int j = 0; j < 4; j++) acc[i][j] = 0ull;

#pragma unroll 2
    for (int k = 0; k < H; k++) {
        const u64* wr = (const u64*)(sW1 + k * H + c0);
        const u64 w0 = wr[0], w1 = wr[1], w2 = wr[2], w3 = wr[3];
#pragma unroll
        for (int i = 0; i < 4; i++) {
            const u64 a = dup2(sIn[(e0 + i) * 132 + k]);
            ffma2(acc[i][0], a, w0); ffma2(acc[i][1], a, w1);
            ffma2(acc[i][2], a, w2); ffma2(acc[i][3], a, w3);
        }
    }
    __syncthreads();

    float* sH = sIn;  // overlay
#pragma unroll
    for (int i = 0; i < 4; i++) {
        float* hrow = sH + (e0 + i) * 132 + c0;
#pragma unroll
        for (int j = 0; j < 4; j++) {
            const float2 v = unpk(acc[i][j]);
            hrow[2 * j]     = fmaxf(v.x + b1r[2 * j],     0.f);
            hrow[2 * j + 1] = fmaxf(v.y + b1r[2 * j + 1], 0.f);
        }
    }
    __syncthreads();

    // ---- layer 2
    u64 acc2[4][2];
#pragma unroll
    for (int i = 0; i < 4; i++) { acc2[i][0] = 0ull; acc2[i][1] = 0ull; }

#pragma unroll 2
    for (int k = 0; k < H; k++) {
        const u64* wr = (const u64*)(sW2 + k * D + c2);
        const u64 w0 = wr[0], w1 = wr[1];
#pragma unroll
        for (int i = 0; i < 4; i++) {
            const u64 a = dup2(sH[(e0 + i) * 132 + k]);
            ffma2(acc2[i][0], a, w0); ffma2(acc2[i][1], a, w1);
        }
    }

#pragma unroll
    for (int i = 0; i < 4; i++) {
        const int g = base + e0 + i;
        if (g < N) {
            const float2 p = unpk(acc2[i][0]);
            const float2 q = unpk(acc2[i][1]);
            out4[(size_t)g * 16 + tx] = make_float4(p.x + b2r[0], p.y + b2r[1],
                                                    q.x + b2r[2], q.y + b2r[3]);
        }
    }
}

// ---------------------------------------------------------------------------
extern "C" void kernel_launch(void* const* d_in, const int* in_sizes, int n_in,
                              void* d_out, int out_size)
{
    const float* node_feats = (const float*)d_in[0];
    const float* edge_feats = (const float*)d_in[1];
    const float* We1 = (const float*)d_in[2];
    const float* be1 = (const float*)d_in[3];
    const float* We2 = (const float*)d_in[4];
    const float* be2 = (const float*)d_in[5];
    const float* Wn1 = (const float*)d_in[6];
    const float* bn1 = (const float*)d_in[7];
    const float* Wn2 = (const float*)d_in[8];
    const float* bn2 = (const float*)d_in[9];
    const int* senders   = (const int*)d_in[10];
    const int* receivers = (const int*)d_in[11];

    const int N = in_sizes[0] / D;
    const int E = in_sizes[1] / D;

    float* out   = (float*)d_out;
    float* e_out = out;                   // [E, D]
    float* n_out = out + (size_t)E * D;   // [N, D]

    cudaFuncSetAttribute(edge_kernel, cudaFuncAttributeMaxDynamicSharedMemorySize, EDGE_SMEM);
    cudaFuncSetAttribute(node_kernel, cudaFuncAttributeMaxDynamicSharedMemorySize, NODE_SMEM);

    int dev = 0, sms = 148;
    cudaGetDevice(&dev);
    cudaDeviceGetAttribute(&sms, cudaDevAttrMultiProcessorCount, dev);

    // 1) zero the aggregation buffer
    const int n4 = N * D / 4;
    zero_agg_kernel<<<(n4 + NTHREADS - 1) / NTHREADS, NTHREADS>>>(n4);

    // 2) edge MLP + scatter-add (persistent)
    edge_kernel<<<sms, NTHREADS, EDGE_SMEM>>>(node_feats, edge_feats,
                                              We1, be1, We2, be2,
                                              senders, receivers, e_out, E, N);

    // 3) node MLP
    node_kernel<<<(N + TM - 1) / TM, NTHREADS, NODE_SMEM>>>(node_feats,
                                                            Wn1, bn1, Wn2, bn2,
                                                            n_out, N);
}

// round 4
// speedup vs baseline: 2.2477x; 2.2477x over previous
#include <cuda_runtime.h>
#include <cuda_bf16.h>

// Problem constants (fixed dataset: N=50000, E=800000, D=64, H=128)
#define D  64
#define H  128
#define TME 128          // edges per tile
#define NTM 64           // nodes per tile (fp32 kernels)
#define NTHREADS 256
#define MAXN 50000

#define SA1_STRIDE 72    // bf16 elems per row (64 + 8 pad)
#define SH_STRIDE  136   // bf16 elems per row (128 + 8 pad)

// Scratch
__device__ float g_agg[MAXN * D];      // segment_sum target
__device__ float g_P[MAXN * 256];      // [node][0:128]=nf@We1_s, [128:256]=nf@We1_r

typedef unsigned int u32;
typedef unsigned long long u64;

// single extern shared symbol for all kernels
extern __shared__ char smem_raw[];

// ============================================================================
__device__ __forceinline__ u32 smem_u32(const void* p) {
    u32 a; asm("{ .reg .u64 t; cvta.to.shared.u64 t, %1; cvt.u32.u64 %0, t; }" : "=r"(a) : "l"(p));
    return a;
}
// pack two fp32 -> bf16x2 {low=lo, high=hi}
__device__ __forceinline__ u32 pack_bf2(float lo, float hi) {
    u32 r; asm("cvt.rn.bf16x2.f32 %0, %1, %2;" : "=r"(r) : "f"(hi), "f"(lo)); return r;
}
__device__ __forceinline__ float lowf(u32 p)  { return __uint_as_float(p << 16); }
__device__ __forceinline__ float highf(u32 p) { return __uint_as_float(p & 0xFFFF0000u); }

__device__ __forceinline__ void ldsm4(u32* r, u32 addr) {
    asm volatile("ldmatrix.sync.aligned.m8n8.x4.shared.b16 {%0,%1,%2,%3}, [%4];"
        : "=r"(r[0]), "=r"(r[1]), "=r"(r[2]), "=r"(r[3]) : "r"(addr));
}
__device__ __forceinline__ void mma_bf(float* c, const u32* a, const u32* b) {
    asm volatile("mma.sync.aligned.m16n8k16.row.col.f32.bf16.bf16.f32 "
        "{%0,%1,%2,%3}, {%4,%5,%6,%7}, {%8,%9}, {%0,%1,%2,%3};"
        : "+f"(c[0]), "+f"(c[1]), "+f"(c[2]), "+f"(c[3])
        : "r"(a[0]), "r"(a[1]), "r"(a[2]), "r"(a[3]), "r"(b[0]), "r"(b[1]));
}

// ---- packed f32x2 helpers (fp32 kernels) ----
__device__ __forceinline__ u64 dup2(float x) {
    u64 r; asm("mov.b64 %0, {%1, %1};" : "=l"(r) : "f"(x)); return r;
}
__device__ __forceinline__ void ffma2(u64 &d, u64 a, u64 b) {
    asm("fma.rn.f32x2 %0, %1, %2, %0;" : "+l"(d) : "l"(a), "l"(b));
}
__device__ __forceinline__ float2 unpk(u64 p) {
    float lo, hi; asm("mov.b64 {%0, %1}, %2;" : "=f"(lo), "=f"(hi) : "l"(p));
    return make_float2(lo, hi);
}

// ============================================================================
__global__ void zero_agg_kernel(int n4) {
    int i = blockIdx.x * blockDim.x + threadIdx.x;
    if (i < n4) reinterpret_cast<float4*>(g_agg)[i] = make_float4(0.f, 0.f, 0.f, 0.f);
}

// ============================================================================
// P projection: g_P[n][c] = sum_k nf[n][k] * We1[64+k][c] (c<128) / We1[128+k][c-128]
#define P_SMEM ((64*256 + 64*68) * 4)
__global__ __launch_bounds__(NTHREADS)
void pproj_kernel(const float* __restrict__ nodef, const float* __restrict__ We1, int N)
{
    float* sm = (float*)smem_raw;
    float* sW  = sm;              // [64][256]
    float* sIn = sm + 64 * 256;   // [64][68]
    const int tid = threadIdx.x;
    const int base = blockIdx.x * NTM;

    for (int i = tid; i < 64 * 256; i += NTHREADS) {
        int k = i >> 8, c = i & 255;
        sW[i] = (c < 128) ? We1[(64 + k) * 128 + c] : We1[(128 + k) * 128 + (c - 128)];
    }
    {
        const int le = tid >> 2, q = tid & 3;
        int g = base + le; if (g >= N) g = N - 1;
        float4* row = (float4*)(sIn + le * 68);
        const float4* src = (const float4*)(nodef + (size_t)g * 64);
#pragma unroll
        for (int j = 0; j < 4; j++) row[q + 4 * j] = src[q + 4 * j];
    }
    __syncthreads();

    const int ty = tid >> 4, tx = tid & 15;
    const int r0 = ty * 4, c0 = tx * 16;
    u64 acc[4][8];
#pragma unroll
    for (int i = 0; i < 4; i++)
#pragma unroll
        for (int j = 0; j < 8; j++) acc[i][j] = 0ull;

#pragma unroll 2
    for (int k = 0; k < 64; k++) {
        const u64* wr = (const u64*)(sW + k * 256 + c0);
        u64 w[8];
#pragma unroll
        for (int j = 0; j < 8; j++) w[j] = wr[j];
#pragma unroll
        for (int i = 0; i < 4; i++) {
            const u64 a = dup2(sIn[(r0 + i) * 68 + k]);
#pragma unroll
            for (int j = 0; j < 8; j++) ffma2(acc[i][j], a, w[j]);
        }
    }
#pragma unroll
    for (int i = 0; i < 4; i++) {
        const int g = base + r0 + i;
        if (g < N) {
            float4* out = (float4*)(g_P + (size_t)g * 256 + c0);
#pragma unroll
            for (int j = 0; j < 4; j++) {
                const float2 a = unpk(acc[i][2 * j]), b = unpk(acc[i][2 * j + 1]);
                out[j] = make_float4(a.x, a.y, b.x, b.y);
            }
        }
    }
}

// ============================================================================
// Edge kernel: mma.sync bf16 3-term split, persistent, weight frags in regs.
// smem byte offsets:
//   sSS[128] @ 0, sSR[128] @ 512
//   A1 hi @ 1024  (128 x 72 bf16 = 18432B), A1 lo @ 19456
//   H  hi @ 37888 (128 x 136 bf16 = 34816B), H lo @ 72704
#define EDGE_SMEM (72704 + 34816)

__global__ __launch_bounds__(NTHREADS, 1)
void edge_kernel(const float* __restrict__ edgef,
                 const float* __restrict__ We1, const float* __restrict__ be1,
                 const float* __restrict__ We2, const float* __restrict__ be2,
                 const int* __restrict__ senders, const int* __restrict__ recvs,
                 float* __restrict__ e_out, int E)
{
    char* sm = smem_raw;
    int* sSS = (int*)sm;
    int* sSR = (int*)(sm + 512);
    const u32 smb = smem_u32(sm);
    const u32 a1h = smb + 1024, a1l = smb + 19456;
    const u32 hhb = smb + 37888, hlb = smb + 72704;

    const int tid = threadIdx.x, wid = tid >> 5, lid = tid & 31;
    const int nrow = lid >> 2;        // fragment row/col lane index
    const int cq   = (lid & 3) * 2;   // fragment col-pair base

    // ---- build weight fragments into registers (once per CTA) ----
    u32 b1h[2][4][2], b1l[2][4][2];
#pragma unroll
    for (int nt = 0; nt < 2; nt++) {
        const int n = wid * 16 + nt * 8 + nrow;
#pragma unroll
        for (int kt = 0; kt < 4; kt++) {
#pragma unroll
            for (int r = 0; r < 2; r++) {
                const int k = kt * 16 + cq + r * 8;
                const float w0 = We1[k * 128 + n];
                const float w1 = We1[(k + 1) * 128 + n];
                const u32 hp = pack_bf2(w0, w1);
                b1h[nt][kt][r] = hp;
                b1l[nt][kt][r] = pack_bf2(w0 - lowf(hp), w1 - highf(hp));
            }
        }
    }
    u32 b2h[8][2], b2l[8][2];
    {
        const int n = wid * 8 + nrow;
#pragma unroll
        for (int kt = 0; kt < 8; kt++) {
#pragma unroll
            for (int r = 0; r < 2; r++) {
                const int k = kt * 16 + cq + r * 8;
                const float w0 = We2[k * 64 + n];
                const float w1 = We2[(k + 1) * 64 + n];
                const u32 hp = pack_bf2(w0, w1);
                b2h[kt][r] = hp;
                b2l[kt][r] = pack_bf2(w0 - lowf(hp), w1 - highf(hp));
            }
        }
    }
    // biases for this thread's output columns
    float2 bb1[2], bb2;
    bb1[0] = *(const float2*)(be1 + wid * 16 + cq);
    bb1[1] = *(const float2*)(be1 + wid * 16 + 8 + cq);
    bb2    = *(const float2*)(be2 + wid * 8 + cq);

    // ldmatrix per-thread offsets
    const int trow = (lid & 7) + ((lid >> 3) & 1) * 8;
    const int tcol = (lid >> 4) * 8;
    const u32 offA = (u32)(trow * SA1_STRIDE + tcol) * 2;
    const u32 offH = (u32)(trow * SH_STRIDE + tcol) * 2;

    const int nTiles = (E + TME - 1) / TME;

    for (int tile = blockIdx.x; tile < nTiles; tile += gridDim.x) {
        const int base = tile * TME;
        __syncthreads();   // previous tile done with all smem

        // ---- stage indices ----
        if (tid < 128) {
            int g = base + tid; if (g >= E) g = E - 1;
            sSS[tid] = senders[g];
            sSR[tid] = recvs[g];
        }
        // ---- stage A1 = ef tile (bf16 hi/lo) ----
        {
            const int row = tid >> 1, half = tid & 1;
            int ge = base + row; if (ge >= E) ge = E - 1;
            const float4* src = (const float4*)(edgef + (size_t)ge * 64 + half * 32);
            u32* dh = (u32*)(sm + 1024  + (row * SA1_STRIDE + half * 32) * 2);
            u32* dl = (u32*)(sm + 19456 + (row * SA1_STRIDE + half * 32) * 2);
#pragma unroll
            for (int j = 0; j < 8; j++) {
                const float4 v = src[j];
                const u32 h0 = pack_bf2(v.x, v.y);
                const u32 h1 = pack_bf2(v.z, v.w);
                dh[2 * j]     = h0;
                dh[2 * j + 1] = h1;
                dl[2 * j]     = pack_bf2(v.x - lowf(h0), v.y - highf(h0));
                dl[2 * j + 1] = pack_bf2(v.z - lowf(h1), v.w - highf(h1));
            }
        }
        __syncthreads();

        // ---- layer 1: acc1[128,128] = A1 @ W1^T (+bias in init) ----
        float acc1[8][2][4];
#pragma unroll
        for (int mt = 0; mt < 8; mt++)
#pragma unroll
            for (int nt = 0; nt < 2; nt++) {
                acc1[mt][nt][0] = bb1[nt].x; acc1[mt][nt][1] = bb1[nt].y;
                acc1[mt][nt][2] = bb1[nt].x; acc1[mt][nt][3] = bb1[nt].y;
            }

#pragma unroll
        for (int mt = 0; mt < 8; mt++) {
            const u32 bh = a1h + offA + mt * (16 * SA1_STRIDE * 2);
            const u32 bl = a1l + offA + mt * (16 * SA1_STRIDE * 2);
#pragma unroll
            for (int kt = 0; kt < 4; kt++) {
                u32 ah[4], al[4];
                ldsm4(ah, bh + kt * 32);
                ldsm4(al, bl + kt * 32);
#pragma unroll
                for (int nt = 0; nt < 2; nt++) {
                    mma_bf(acc1[mt][nt], ah, b1h[nt][kt]);
                    mma_bf(acc1[mt][nt], ah, b1l[nt][kt]);
                    mma_bf(acc1[mt][nt], al, b1h[nt][kt]);
                }
            }
        }

        // ---- epilogue1: h = relu(acc1 + P1[s] + P2[r]) -> smem (bf16 hi/lo) ----
#pragma unroll
        for (int mt = 0; mt < 8; mt++) {
            const int m0 = mt * 16 + nrow, m1 = m0 + 8;
            const int s0 = sSS[m0], r0 = sSR[m0];
            const int s1 = sSS[m1], r1 = sSR[m1];
#pragma unroll
            for (int nt = 0; nt < 2; nt++) {
                const int n0 = wid * 16 + nt * 8 + cq;
                const float2 p1a = __ldg((const float2*)(g_P + (size_t)s0 * 256 + n0));
                const float2 p2a = __ldg((const float2*)(g_P + (size_t)r0 * 256 + 128 + n0));
                const float2 p1b = __ldg((const float2*)(g_P + (size_t)s1 * 256 + n0));
                const float2 p2b = __ldg((const float2*)(g_P + (size_t)r1 * 256 + 128 + n0));
                const float x0 = fmaxf(acc1[mt][nt][0] + p1a.x + p2a.x, 0.f);
                const float x1 = fmaxf(acc1[mt][nt][1] + p1a.y + p2a.y, 0.f);
                const float x2 = fmaxf(acc1[mt][nt][2] + p1b.x + p2b.x, 0.f);
                const float x3 = fmaxf(acc1[mt][nt][3] + p1b.y + p2b.y, 0.f);
                const u32 h0 = pack_bf2(x0, x1);
                const u32 h1 = pack_bf2(x2, x3);
                *(u32*)(sm + 37888 + (m0 * SH_STRIDE + n0) * 2) = h0;
                *(u32*)(sm + 37888 + (m1 * SH_STRIDE + n0) * 2) = h1;
                *(u32*)(sm + 72704 + (m0 * SH_STRIDE + n0) * 2) =
                    pack_bf2(x0 - lowf(h0), x1 - highf(h0));
                *(u32*)(sm + 72704 + (m1 * SH_STRIDE + n0) * 2) =
                    pack_bf2(x2 - lowf(h1), x3 - highf(h1));
            }
        }
        __syncthreads();

        // ---- layer 2: acc2[128,64] = h @ W2^T (+bias), 2 m-tiles interleaved ----
        float acc2[8][4];
#pragma unroll
        for (int mt = 0; mt < 8; mt++) {
            acc2[mt][0] = bb2.x; acc2[mt][1] = bb2.y;
            acc2[mt][2] = bb2.x; acc2[mt][3] = bb2.y;
        }
#pragma unroll
        for (int mt = 0; mt < 8; mt += 2) {
            const u32 bh0 = hhb + offH + mt * (16 * SH_STRIDE * 2);
            const u32 bl0 = hlb + offH + mt * (16 * SH_STRIDE * 2);
            const u32 bh1 = bh0 + (16 * SH_STRIDE * 2);
            const u32 bl1 = bl0 + (16 * SH_STRIDE * 2);
#pragma unroll
            for (int kt = 0; kt < 8; kt++) {
                u32 ah0[4], al0[4], ah1[4], al1[4];
                ldsm4(ah0, bh0 + kt * 32);
                ldsm4(al0, bl0 + kt * 32);
                ldsm4(ah1, bh1 + kt * 32);
                ldsm4(al1, bl1 + kt * 32);
                mma_bf(acc2[mt],     ah0, b2h[kt]);
                mma_bf(acc2[mt + 1], ah1, b2h[kt]);
                mma_bf(acc2[mt],     ah0, b2l[kt]);
                mma_bf(acc2[mt + 1], ah1, b2l[kt]);
                mma_bf(acc2[mt],     al0, b2h[kt]);
                mma_bf(acc2[mt + 1], al1, b2h[kt]);
            }
        }

        // ---- epilogue2: write e + scatter-add agg[receiver] ----
        {
            const int n2 = wid * 8 + cq;
#pragma unroll
            for (int mt = 0; mt < 8; mt++) {
                const int m0 = mt * 16 + nrow, m1 = m0 + 8;
                const int ge0 = base + m0, ge1 = base + m1;
                if (ge0 < E) {
                    const float2 v0 = make_float2(acc2[mt][0], acc2[mt][1]);
                    *(float2*)(e_out + (size_t)ge0 * 64 + n2) = v0;
                    atomicAdd((float2*)(g_agg + (size_t)sSR[m0] * 64 + n2), v0);
                }
                if (ge1 < E) {
                    const float2 v1 = make_float2(acc2[mt][2], acc2[mt][3]);
                    *(float2*)(e_out + (size_t)ge1 * 64 + n2) = v1;
                    atomicAdd((float2*)(g_agg + (size_t)sSR[m1] * 64 + n2), v1);
                }
            }
        }
    }
}

// ============================================================================
// Node MLP (fp32, f32x2): n = relu([agg|nf] @ Wn1 + bn1) @ Wn2 + bn2
#define NODE_SMEM ((H*H + H*D + NTM*132) * 4)
__global__ __launch_bounds__(NTHREADS, 1)
void node_kernel(const float* __restrict__ nodef,
                 const float* __restrict__ Wn1, const float* __restrict__ bn1,
                 const float* __restrict__ Wn2, const float* __restrict__ bn2,
                 float* __restrict__ n_out, int N)
{
    float* sm = (float*)smem_raw;
    float* sW1 = sm;
    float* sW2 = sm + H * H;
    float* sIn = sW2 + H * D;

    const int tid = threadIdx.x;
    {
        float4* dw = (float4*)sW1; const float4* sw = (const float4*)Wn1;
        for (int i = tid; i < H * H / 4; i += NTHREADS) dw[i] = sw[i];
        float4* dw2 = (float4*)sW2; const float4* sw2 = (const float4*)Wn2;
        for (int i = tid; i < H * D / 4; i += NTHREADS) dw2[i] = sw2[i];
    }
    const int ty = tid >> 4, tx = tid & 15;
    const int e0 = ty * 4, c0 = tx * 8, c2 = tx * 4;
    const int base = blockIdx.x * NTM;

    float b1r[8], b2r[4];
#pragma unroll
    for (int j = 0; j < 8; j++) b1r[j] = bn1[c0 + j];
#pragma unroll
    for (int j = 0; j < 4; j++) b2r[j] = bn2[c2 + j];

    {
        const int le = tid >> 2, q = tid & 3;
        int g = base + le; if (g >= N) g = N - 1;
        float4* rw = (float4*)(sIn + le * 132);
        const float4* ag = (const float4*)(g_agg + (size_t)g * 64);
        const float4* nf = (const float4*)(nodef + (size_t)g * 64);
#pragma unroll
        for (int j = 0; j < 4; j++) rw[q + 4 * j]      = ag[q + 4 * j];
#pragma unroll
        for (int j = 0; j < 4; j++) rw[16 + q + 4 * j] = nf[q + 4 * j];
    }
    __syncthreads();

    u64 acc[4][4];
#pragma unroll
    for (int i = 0; i < 4; i++)
#pragma unroll
        for (int j = 0; j < 4; j++) acc[i][j] = 0ull;

#pragma unroll 2
    for (int k = 0; k < H; k++) {
        const u64* wr = (const u64*)(sW1 + k * H + c0);
        const u64 w0 = wr[0], w1 = wr[1], w2 = wr[2], w3 = wr[3];
#pragma unroll
        for (int i = 0; i < 4; i++) {
            const u64 a = dup2(sIn[(e0 + i) * 132 + k]);
            ffma2(acc[i][0], a, w0); ffma2(acc[i][1], a, w1);
            ffma2(acc[i][2], a, w2); ffma2(acc[i][3], a, w3);
        }
    }
    __syncthreads();

    float* sH = sIn;
#pragma unroll
    for (int i = 0; i < 4; i++) {
        float* hrow = sH + (e0 + i) * 132 + c0;
#pragma unroll
        for (int j = 0; j < 4; j++) {
            const float2 v = unpk(acc[i][j]);
            hrow[2 * j]     = fmaxf(v.x + b1r[2 * j],     0.f);
            hrow[2 * j + 1] = fmaxf(v.y + b1r[2 * j + 1], 0.f);
        }
    }
    __syncthreads();

    u64 acc2[4][2];
#pragma unroll
    for (int i = 0; i < 4; i++) { acc2[i][0] = 0ull; acc2[i][1] = 0ull; }

#pragma unroll 2
    for (int k = 0; k < H; k++) {
        const u64* wr = (const u64*)(sW2 + k * D + c2);
        const u64 w0 = wr[0], w1 = wr[1];
#pragma unroll
        for (int i = 0; i < 4; i++) {
            const u64 a = dup2(sH[(e0 + i) * 132 + k]);
            ffma2(acc2[i][0], a, w0); ffma2(acc2[i][1], a, w1);
        }
    }
#pragma unroll
    for (int i = 0; i < 4; i++) {
        const int g = base + e0 + i;
        if (g < N) {
            const float2 p = unpk(acc2[i][0]);
            const float2 q = unpk(acc2[i][1]);
            ((float4*)(n_out + (size_t)g * 64))[tx] =
                make_float4(p.x + b2r[0], p.y + b2r[1], q.x + b2r[2], q.y + b2r[3]);
        }
    }
}

// ============================================================================
extern "C" void kernel_launch(void* const* d_in, const int* in_sizes, int n_in,
                              void* d_out, int out_size)
{
    const float* node_feats = (const float*)d_in[0];
    const float* edge_feats = (const float*)d_in[1];
    const float* We1 = (const float*)d_in[2];
    const float* be1 = (const float*)d_in[3];
    const float* We2 = (const float*)d_in[4];
    const float* be2 = (const float*)d_in[5];
    const float* Wn1 = (const float*)d_in[6];
    const float* bn1 = (const float*)d_in[7];
    const float* Wn2 = (const float*)d_in[8];
    const float* bn2 = (const float*)d_in[9];
    const int* senders   = (const int*)d_in[10];
    const int* receivers = (const int*)d_in[11];

    const int N = in_sizes[0] / D;
    const int E = in_sizes[1] / D;

    float* out   = (float*)d_out;
    float* e_out = out;                   // [E, D]
    float* n_out = out + (size_t)E * D;   // [N, D]

    cudaFuncSetAttribute(pproj_kernel, cudaFuncAttributeMaxDynamicSharedMemorySize, P_SMEM);
    cudaFuncSetAttribute(edge_kernel,  cudaFuncAttributeMaxDynamicSharedMemorySize, EDGE_SMEM);
    cudaFuncSetAttribute(node_kernel,  cudaFuncAttributeMaxDynamicSharedMemorySize, NODE_SMEM);

    int dev = 0, sms = 148;
    cudaGetDevice(&dev);
    cudaDeviceGetAttribute(&sms, cudaDevAttrMultiProcessorCount, dev);

    const int n4 = N * D / 4;
    zero_agg_kernel<<<(n4 + NTHREADS - 1) / NTHREADS, NTHREADS>>>(n4);

    pproj_kernel<<<(N + NTM - 1) / NTM, NTHREADS, P_SMEM>>>(node_feats, We1, N);

    edge_kernel<<<sms, NTHREADS, EDGE_SMEM>>>(edge_feats, We1, be1, We2, be2,
                                              senders, receivers, e_out, E);

    node_kernel<<<(N + NTM - 1) / NTM, NTHREADS, NODE_SMEM>>>(node_feats,
                                                              Wn1, bn1, Wn2, bn2,
                                                              n_out, N);
}

// round 5
// speedup vs baseline: 3.2247x; 1.4347x over previous
#include <cuda_runtime.h>
#include <cuda_bf16.h>

// Problem constants (fixed dataset: N=50000, E=800000, D=64, H=128)
#define D  64
#define H  128
#define MAXN 50000

#define SA_STRIDE 72     // bf16 elems per row (64 + 8 pad)
#define SH_STRIDE 136    // bf16 elems per row (128 + 8 pad)

// Scratch
__device__ float g_agg[MAXN * D];      // segment_sum target
__device__ float g_P[MAXN * 384];      // [0:128]=nf@We1_s, [128:256]=nf@We1_r, [256:384]=nf@Wn1_n

typedef unsigned int u32;
typedef unsigned long long u64;

extern __shared__ char smem_raw[];

// shared layout (edge & node kernels):
//   header 1024B (indices), A hi @1024 (18432), A lo @19456 (18432),
//   H hi @37888 (34816), H lo @72704 (34816)  -> total 107520
#define OFF_AH 1024
#define OFF_AL 19456
#define OFF_HH 37888
#define OFF_HL 72704
#define BIG_SMEM 107520
#define PPROJ_SMEM 37888

// ============================================================================
__device__ __forceinline__ u32 smem_u32(const void* p) {
    u32 a; asm("{ .reg .u64 t; cvta.to.shared.u64 t, %1; cvt.u32.u64 %0, t; }" : "=r"(a) : "l"(p));
    return a;
}
// pack two fp32 -> bf16x2 {low=lo, high=hi}
__device__ __forceinline__ u32 pack_bf2(float lo, float hi) {
    u32 r; asm("cvt.rn.bf16x2.f32 %0, %1, %2;" : "=r"(r) : "f"(hi), "f"(lo)); return r;
}
__device__ __forceinline__ float lowf(u32 p)  { return __uint_as_float(p << 16); }
__device__ __forceinline__ float highf(u32 p) { return __uint_as_float(p & 0xFFFF0000u); }

__device__ __forceinline__ void ldsm4(u32* r, u32 addr) {
    asm volatile("ldmatrix.sync.aligned.m8n8.x4.shared.b16 {%0,%1,%2,%3}, [%4];"
        : "=r"(r[0]), "=r"(r[1]), "=r"(r[2]), "=r"(r[3]) : "r"(addr));
}
__device__ __forceinline__ void mma_bf(float* c, const u32* a, const u32* b) {
    asm volatile("mma.sync.aligned.m16n8k16.row.col.f32.bf16.bf16.f32 "
        "{%0,%1,%2,%3}, {%4,%5,%6,%7}, {%8,%9}, {%0,%1,%2,%3};"
        : "+f"(c[0]), "+f"(c[1]), "+f"(c[2]), "+f"(c[3])
        : "r"(a[0]), "r"(a[1]), "r"(a[2]), "r"(a[3]), "r"(b[0]), "r"(b[1]));
}
// build bf16 hi/lo B-fragment pair from W[k0*ldw+n], W[(k0+1)*ldw+n]
__device__ __forceinline__ void build_frag(const float* __restrict__ W, int ldw,
                                           int n, int k0, u32& hi, u32& lo) {
    const float w0 = W[k0 * ldw + n];
    const float w1 = W[(k0 + 1) * ldw + n];
    hi = pack_bf2(w0, w1);
    lo = pack_bf2(w0 - lowf(hi), w1 - highf(hi));
}
// stage 4 float4 (one quarter-row) as bf16 hi/lo into smem A buffers
__device__ __forceinline__ void stage_row_quarter(char* sm, const float4* src4,
                                                  int row, int q) {
#pragma unroll
    for (int j = 0; j < 4; j++) {
        const float4 v = src4[q + 4 * j];
        const int col = (q + 4 * j) * 4;               // float index in row
        const u32 off = (u32)(row * SA_STRIDE + col) * 2;
        const u32 h0 = pack_bf2(v.x, v.y);
        const u32 h1 = pack_bf2(v.z, v.w);
        *(u32*)(sm + OFF_AH + off)     = h0;
        *(u32*)(sm + OFF_AH + off + 4) = h1;
        *(u32*)(sm + OFF_AL + off)     = pack_bf2(v.x - lowf(h0), v.y - highf(h0));
        *(u32*)(sm + OFF_AL + off + 4) = pack_bf2(v.z - lowf(h1), v.w - highf(h1));
    }
}

// ============================================================================
__global__ void zero_agg_kernel(int n4) {
    int i = blockIdx.x * blockDim.x + threadIdx.x;
    if (i < n4) reinterpret_cast<float4*>(g_agg)[i] = make_float4(0.f, 0.f, 0.f, 0.f);
}

// ============================================================================
// P projection (mma bf16 3-term): g_P[n][seg*128+c] for seg in {We1_s, We1_r, Wn1_n}
__global__ __launch_bounds__(512)
void pproj_kernel(const float* __restrict__ nodef,
                  const float* __restrict__ We1, const float* __restrict__ Wn1, int N)
{
    char* sm = smem_raw;
    const u32 smb = smem_u32(sm);
    const u32 ahb = smb + OFF_AH, alb = smb + OFF_AL;

    const int tid = threadIdx.x, wid = tid >> 5, lid = tid & 31;
    const int nrow = lid >> 2, cq = (lid & 3) * 2;
    const int base = blockIdx.x * 128;

    // B fragments: 3 segments x 4 k-tiles x 2 regs, hi+lo
    u32 bh[3][4][2], bl[3][4][2];
    {
        const int n = wid * 8 + nrow;
#pragma unroll
        for (int kt = 0; kt < 4; kt++)
#pragma unroll
            for (int r = 0; r < 2; r++) {
                const int k = kt * 16 + cq + r * 8;
                build_frag(We1 + (size_t)64 * 128, 128, n, k, bh[0][kt][r], bl[0][kt][r]);
                build_frag(We1 + (size_t)128 * 128, 128, n, k, bh[1][kt][r], bl[1][kt][r]);
                build_frag(Wn1 + (size_t)64 * 128, 128, n, k, bh[2][kt][r], bl[2][kt][r]);
            }
    }

    // stage A = nf tile [128,64] bf16 hi/lo
    {
        const int row = tid >> 2, q = tid & 3;
        int g = base + row; if (g >= N) g = N - 1;
        stage_row_quarter(sm, (const float4*)(nodef + (size_t)g * 64), row, q);
    }
    __syncthreads();

    const int trow = (lid & 7) + ((lid >> 3) & 1) * 8;
    const int tcol = (lid >> 4) * 8;
    const u32 offA = (u32)(trow * SA_STRIDE + tcol) * 2;
    const int n0 = wid * 8 + cq;

#pragma unroll
    for (int mt = 0; mt < 8; mt++) {
        u32 ah[4][4], al[4][4];
        const u32 bhA = ahb + offA + mt * (16 * SA_STRIDE * 2);
        const u32 blA = alb + offA + mt * (16 * SA_STRIDE * 2);
#pragma unroll
        for (int kt = 0; kt < 4; kt++) {
            ldsm4(ah[kt], bhA + kt * 32);
            ldsm4(al[kt], blA + kt * 32);
        }
        const int g0 = base + mt * 16 + nrow, g1 = g0 + 8;
#pragma unroll
        for (int seg = 0; seg < 3; seg++) {
            float acc[4] = {0.f, 0.f, 0.f, 0.f};
#pragma unroll
            for (int kt = 0; kt < 4; kt++) {
                mma_bf(acc, ah[kt], bh[seg][kt]);
                mma_bf(acc, ah[kt], bl[seg][kt]);
                mma_bf(acc, al[kt], bh[seg][kt]);
            }
            if (g0 < N) *(float2*)(g_P + (size_t)g0 * 384 + seg * 128 + n0) =
                            make_float2(acc[0], acc[1]);
            if (g1 < N) *(float2*)(g_P + (size_t)g1 * 384 + seg * 128 + n0) =
                            make_float2(acc[2], acc[3]);
        }
    }
}

// ============================================================================
// Edge kernel: persistent, 512 threads, mma bf16 3-term split.
__global__ __launch_bounds__(512, 1)
void edge_kernel(const float* __restrict__ edgef,
                 const float* __restrict__ We1, const float* __restrict__ be1,
                 const float* __restrict__ We2, const float* __restrict__ be2,
                 const int* __restrict__ senders, const int* __restrict__ recvs,
                 float* __restrict__ e_out, int E)
{
    char* sm = smem_raw;
    int* sSS = (int*)sm;
    int* sSR = (int*)(sm + 512);
    float* sF = (float*)(sm + OFF_AH);   // epilogue2 fp32 staging [128][68] (reuses A area)
    const u32 smb = smem_u32(sm);
    const u32 ahb = smb + OFF_AH, alb = smb + OFF_AL;
    const u32 hhb = smb + OFF_HH, hlb = smb + OFF_HL;

    const int tid = threadIdx.x, wid = tid >> 5, lid = tid & 31;
    const int nrow = lid >> 2, cq = (lid & 3) * 2;
    const int mh = wid >> 3;              // layer2 m-half

    // ---- weight fragments (once per CTA) ----
    u32 b1h[4][2], b1l[4][2];
    {
        const int n = wid * 8 + nrow;
#pragma unroll
        for (int kt = 0; kt < 4; kt++)
#pragma unroll
            for (int r = 0; r < 2; r++)
                build_frag(We1, 128, n, kt * 16 + cq + r * 8, b1h[kt][r], b1l[kt][r]);
    }
    u32 b2h[8][2], b2l[8][2];
    {
        const int n = (wid & 7) * 8 + nrow;
#pragma unroll
        for (int kt = 0; kt < 8; kt++)
#pragma unroll
            for (int r = 0; r < 2; r++)
                build_frag(We2, 64, n, kt * 16 + cq + r * 8, b2h[kt][r], b2l[kt][r]);
    }
    const float2 bb1 = *(const float2*)(be1 + wid * 8 + cq);
    const float2 bb2 = *(const float2*)(be2 + (wid & 7) * 8 + cq);

    const int trow = (lid & 7) + ((lid >> 3) & 1) * 8;
    const int tcol = (lid >> 4) * 8;
    const u32 offA = (u32)(trow * SA_STRIDE + tcol) * 2;
    const u32 offH = (u32)(trow * SH_STRIDE + tcol) * 2;

    const int nTiles = (E + 127) / 128;

    for (int tile = blockIdx.x; tile < nTiles; tile += gridDim.x) {
        const int base = tile * 128;
        __syncthreads();   // previous tile fully done with smem

        // ---- stage indices + A (ef tile, bf16 hi/lo) ----
        if (tid < 128) {
            int g = base + tid; if (g >= E) g = E - 1;
            sSS[tid] = senders[g];
            sSR[tid] = recvs[g];
        }
        {
            const int row = tid >> 2, q = tid & 3;
            int ge = base + row; if (ge >= E) ge = E - 1;
            stage_row_quarter(sm, (const float4*)(edgef + (size_t)ge * 64), row, q);
        }
        __syncthreads();

        // ---- layer 1: acc1[128,128] = A @ We1_e^T (+be1) ----
        float acc1[8][4];
#pragma unroll
        for (int mt = 0; mt < 8; mt++) {
            acc1[mt][0] = bb1.x; acc1[mt][1] = bb1.y;
            acc1[mt][2] = bb1.x; acc1[mt][3] = bb1.y;
        }
#pragma unroll
        for (int mt = 0; mt < 8; mt++) {
            const u32 bh = ahb + offA + mt * (16 * SA_STRIDE * 2);
            const u32 bl = alb + offA + mt * (16 * SA_STRIDE * 2);
#pragma unroll
            for (int kt = 0; kt < 4; kt++) {
                u32 ah[4], al[4];
                ldsm4(ah, bh + kt * 32);
                ldsm4(al, bl + kt * 32);
                mma_bf(acc1[mt], ah, b1h[kt]);
                mma_bf(acc1[mt], ah, b1l[kt]);
                mma_bf(acc1[mt], al, b1h[kt]);
            }
        }

        // ---- epilogue1: h = relu(acc1 + P1[s] + P2[r]) -> smem bf16 hi/lo ----
        {
            const int n0 = wid * 8 + cq;
#pragma unroll
            for (int half = 0; half < 2; half++) {
                float2 p1a[4], p2a[4], p1b[4], p2b[4];
#pragma unroll
                for (int i = 0; i < 4; i++) {
                    const int mt = half * 4 + i;
                    const int m0 = mt * 16 + nrow, m1 = m0 + 8;
                    p1a[i] = __ldg((const float2*)(g_P + (size_t)sSS[m0] * 384 + n0));
                    p2a[i] = __ldg((const float2*)(g_P + (size_t)sSR[m0] * 384 + 128 + n0));
                    p1b[i] = __ldg((const float2*)(g_P + (size_t)sSS[m1] * 384 + n0));
                    p2b[i] = __ldg((const float2*)(g_P + (size_t)sSR[m1] * 384 + 128 + n0));
                }
#pragma unroll
                for (int i = 0; i < 4; i++) {
                    const int mt = half * 4 + i;
                    const int m0 = mt * 16 + nrow, m1 = m0 + 8;
                    const float x0 = fmaxf(acc1[mt][0] + p1a[i].x + p2a[i].x, 0.f);
                    const float x1 = fmaxf(acc1[mt][1] + p1a[i].y + p2a[i].y, 0.f);
                    const float x2 = fmaxf(acc1[mt][2] + p1b[i].x + p2b[i].x, 0.f);
                    const float x3 = fmaxf(acc1[mt][3] + p1b[i].y + p2b[i].y, 0.f);
                    const u32 h0 = pack_bf2(x0, x1);
                    const u32 h1 = pack_bf2(x2, x3);
                    *(u32*)(sm + OFF_HH + (m0 * SH_STRIDE + n0) * 2) = h0;
                    *(u32*)(sm + OFF_HH + (m1 * SH_STRIDE + n0) * 2) = h1;
                    *(u32*)(sm + OFF_HL + (m0 * SH_STRIDE + n0) * 2) =
                        pack_bf2(x0 - lowf(h0), x1 - highf(h0));
                    *(u32*)(sm + OFF_HL + (m1 * SH_STRIDE + n0) * 2) =
                        pack_bf2(x2 - lowf(h1), x3 - highf(h1));
                }
            }
        }
        __syncthreads();

        // ---- layer 2: acc2[128,64] = h @ We2^T (+be2) ----
        float acc2[4][4];
#pragma unroll
        for (int mt = 0; mt < 4; mt++) {
            acc2[mt][0] = bb2.x; acc2[mt][1] = bb2.y;
            acc2[mt][2] = bb2.x; acc2[mt][3] = bb2.y;
        }
#pragma unroll
        for (int mt = 0; mt < 4; mt++) {
            const int rowbase = (mh * 4 + mt) * 16;
            const u32 bh = hhb + offH + rowbase * (SH_STRIDE * 2);
            const u32 bl = hlb + offH + rowbase * (SH_STRIDE * 2);
#pragma unroll
            for (int kt = 0; kt < 8; kt++) {
                u32 ah[4], al[4];
                ldsm4(ah, bh + kt * 32);
                ldsm4(al, bl + kt * 32);
                mma_bf(acc2[mt], ah, b2h[kt]);
                mma_bf(acc2[mt], ah, b2l[kt]);
                mma_bf(acc2[mt], al, b2h[kt]);
            }
        }

        // ---- epilogue2: stage to smem fp32, then float4 stores + atomics ----
        {
            const int n2 = (wid & 7) * 8 + cq;
#pragma unroll
            for (int mt = 0; mt < 4; mt++) {
                const int m0 = mh * 64 + mt * 16 + nrow, m1 = m0 + 8;
                *(float2*)(sF + m0 * 68 + n2) = make_float2(acc2[mt][0], acc2[mt][1]);
                *(float2*)(sF + m1 * 68 + n2) = make_float2(acc2[mt][2], acc2[mt][3]);
            }
        }
        __syncthreads();
        {
            const int row = tid >> 2, q = tid & 3;
            const int ge = base + row;
            if (ge < E) {
                const int ridx = sSR[row];
#pragma unroll
                for (int j = 0; j < 4; j++) {
                    const int col = (q + 4 * j) * 4;
                    const float4 v = *(const float4*)(sF + row * 68 + col);
                    *(float4*)(e_out + (size_t)ge * 64 + col) = v;
                    atomicAdd((float4*)(g_agg + (size_t)ridx * 64 + col), v);
                }
            }
        }
    }
}

// ============================================================================
// Node kernel: n = relu(agg@Wn1_a + Q[node] + bn1) @ Wn2 + bn2  (mma bf16 3-term)
__global__ __launch_bounds__(512, 1)
void node_kernel(const float* __restrict__ Wn1, const float* __restrict__ bn1,
                 const float* __restrict__ Wn2, const float* __restrict__ bn2,
                 float* __restrict__ n_out, int N)
{
    char* sm = smem_raw;
    const u32 smb = smem_u32(sm);
    const u32 ahb = smb + OFF_AH, alb = smb + OFF_AL;
    const u32 hhb = smb + OFF_HH, hlb = smb + OFF_HL;

    const int tid = threadIdx.x, wid = tid >> 5, lid = tid & 31;
    const int nrow = lid >> 2, cq = (lid & 3) * 2;
    const int mh = wid >> 3;
    const int base = blockIdx.x * 128;

    // weight fragments
    u32 b1h[4][2], b1l[4][2];
    {
        const int n = wid * 8 + nrow;
#pragma unroll
        for (int kt = 0; kt < 4; kt++)
#pragma unroll
            for (int r = 0; r < 2; r++)
                build_frag(Wn1, 128, n, kt * 16 + cq + r * 8, b1h[kt][r], b1l[kt][r]);
    }
    u32 b2h[8][2], b2l[8][2];
    {
        const int n = (wid & 7) * 8 + nrow;
#pragma unroll
        for (int kt = 0; kt < 8; kt++)
#pragma unroll
            for (int r = 0; r < 2; r++)
                build_frag(Wn2, 64, n, kt * 16 + cq + r * 8, b2h[kt][r], b2l[kt][r]);
    }
    const float2 bb1 = *(const float2*)(bn1 + wid * 8 + cq);
    const float2 bb2 = *(const float2*)(bn2 + (wid & 7) * 8 + cq);

    const int trow = (lid & 7) + ((lid >> 3) & 1) * 8;
    const int tcol = (lid >> 4) * 8;
    const u32 offA = (u32)(trow * SA_STRIDE + tcol) * 2;
    const u32 offH = (u32)(trow * SH_STRIDE + tcol) * 2;

    // stage A = agg tile [128,64] bf16 hi/lo
    {
        const int row = tid >> 2, q = tid & 3;
        int g = base + row; if (g >= N) g = N - 1;
        stage_row_quarter(sm, (const float4*)(g_agg + (size_t)g * 64), row, q);
    }
    __syncthreads();

    // layer 1
    float acc1[8][4];
#pragma unroll
    for (int mt = 0; mt < 8; mt++) {
        acc1[mt][0] = bb1.x; acc1[mt][1] = bb1.y;
        acc1[mt][2] = bb1.x; acc1[mt][3] = bb1.y;
    }
#pragma unroll
    for (int mt = 0; mt < 8; mt++) {
        const u32 bh = ahb + offA + mt * (16 * SA_STRIDE * 2);
        const u32 bl = alb + offA + mt * (16 * SA_STRIDE * 2);
#pragma unroll
        for (int kt = 0; kt < 4; kt++) {
            u32 ah[4], al[4];
            ldsm4(ah, bh + kt * 32);
            ldsm4(al, bl + kt * 32);
            mma_bf(acc1[mt], ah, b1h[kt]);
            mma_bf(acc1[mt], ah, b1l[kt]);
            mma_bf(acc1[mt], al, b1h[kt]);
        }
    }

    // epilogue1: h = relu(acc1 + Q[node])
    {
        const int n0 = wid * 8 + cq;
#pragma unroll
        for (int mt = 0; mt < 8; mt++) {
            const int m0 = mt * 16 + nrow, m1 = m0 + 8;
            int g0 = base + m0; if (g0 >= N) g0 = N - 1;
            int g1 = base + m1; if (g1 >= N) g1 = N - 1;
            const float2 qa = __ldg((const float2*)(g_P + (size_t)g0 * 384 + 256 + n0));
            const float2 qb = __ldg((const float2*)(g_P + (size_t)g1 * 384 + 256 + n0));
            const float x0 = fmaxf(acc1[mt][0] + qa.x, 0.f);
            const float x1 = fmaxf(acc1[mt][1] + qa.y, 0.f);
            const float x2 = fmaxf(acc1[mt][2] + qb.x, 0.f);
            const float x3 = fmaxf(acc1[mt][3] + qb.y, 0.f);
            const u32 h0 = pack_bf2(x0, x1);
            const u32 h1 = pack_bf2(x2, x3);
            *(u32*)(sm + OFF_HH + (m0 * SH_STRIDE + n0) * 2) = h0;
            *(u32*)(sm + OFF_HH + (m1 * SH_STRIDE + n0) * 2) = h1;
            *(u32*)(sm + OFF_HL + (m0 * SH_STRIDE + n0) * 2) =
                pack_bf2(x0 - lowf(h0), x1 - highf(h0));
            *(u32*)(sm + OFF_HL + (m1 * SH_STRIDE + n0) * 2) =
                pack_bf2(x2 - lowf(h1), x3 - highf(h1));
        }
    }
    __syncthreads();

    // layer 2
    float acc2[4][4];
#pragma unroll
    for (int mt = 0; mt < 4; mt++) {
        acc2[mt][0] = bb2.x; acc2[mt][1] = bb2.y;
        acc2[mt][2] = bb2.x; acc2[mt][3] = bb2.y;
    }
#pragma unroll
    for (int mt = 0; mt < 4; mt++) {
        const int rowbase = (mh * 4 + mt) * 16;
        const u32 bh = hhb + offH + rowbase * (SH_STRIDE * 2);
        const u32 bl = hlb + offH + rowbase * (SH_STRIDE * 2);
#pragma unroll
        for (int kt = 0; kt < 8; kt++) {
            u32 ah[4], al[4];
            ldsm4(ah, bh + kt * 32);
            ldsm4(al, bl + kt * 32);
            mma_bf(acc2[mt], ah, b2h[kt]);
            mma_bf(acc2[mt], ah, b2l[kt]);
            mma_bf(acc2[mt], al, b2h[kt]);
        }
    }

    // epilogue2: direct stores
    {
        const int n2 = (wid & 7) * 8 + cq;
#pragma unroll
        for (int mt = 0; mt < 4; mt++) {
            const int m0 = mh * 64 + mt * 16 + nrow, m1 = m0 + 8;
            const int g0 = base + m0, g1 = base + m1;
            if (g0 < N) *(float2*)(n_out + (size_t)g0 * 64 + n2) =
                            make_float2(acc2[mt][0], acc2[mt][1]);
            if (g1 < N) *(float2*)(n_out + (size_t)g1 * 64 + n2) =
                            make_float2(acc2[mt][2], acc2[mt][3]);
        }
    }
}

// ============================================================================
extern "C" void kernel_launch(void* const* d_in, const int* in_sizes, int n_in,
                              void* d_out, int out_size)
{
    const float* node_feats = (const float*)d_in[0];
    const float* edge_feats = (const float*)d_in[1];
    const float* We1 = (const float*)d_in[2];
    const float* be1 = (const float*)d_in[3];
    const float* We2 = (const float*)d_in[4];
    const float* be2 = (const float*)d_in[5];
    const float* Wn1 = (const float*)d_in[6];
    const float* bn1 = (const float*)d_in[7];
    const float* Wn2 = (const float*)d_in[8];
    const float* bn2 = (const float*)d_in[9];
    const int* senders   = (const int*)d_in[10];
    const int* receivers = (const int*)d_in[11];

    const int N = in_sizes[0] / D;
    const int E = in_sizes[1] / D;

    float* out   = (float*)d_out;
    float* e_out = out;                   // [E, D]
    float* n_out = out + (size_t)E * D;   // [N, D]

    cudaFuncSetAttribute(pproj_kernel, cudaFuncAttributeMaxDynamicSharedMemorySize, PPROJ_SMEM);
    cudaFuncSetAttribute(edge_kernel,  cudaFuncAttributeMaxDynamicSharedMemorySize, BIG_SMEM);
    cudaFuncSetAttribute(node_kernel,  cudaFuncAttributeMaxDynamicSharedMemorySize, BIG_SMEM);

    int dev = 0, sms = 148;
    cudaGetDevice(&dev);
    cudaDeviceGetAttribute(&sms, cudaDevAttrMultiProcessorCount, dev);

    const int n4 = N * D / 4;
    zero_agg_kernel<<<(n4 + 255) / 256, 256>>>(n4);

    const int nodeTiles = (N + 127) / 128;
    pproj_kernel<<<nodeTiles, 512, PPROJ_SMEM>>>(node_feats, We1, Wn1, N);

    edge_kernel<<<sms, 512, BIG_SMEM>>>(edge_feats, We1, be1, We2, be2,
                                        senders, receivers, e_out, E);

    node_kernel<<<nodeTiles, 512, BIG_SMEM>>>(Wn1, bn1, Wn2, bn2, n_out, N);
}

// round 8
// speedup vs baseline: 3.7182x; 1.1530x over previous
#include <cuda_runtime.h>
#include <cuda_bf16.h>

// Problem constants (fixed dataset: N=50000, E=800000, D=64, H=128)
#define D  64
#define H  128
#define MAXN 50000

#define SA_STRIDE 72     // bf16 elems per row (64 + 8 pad)
#define SH_STRIDE 136    // bf16 elems per row (128 + 8 pad)

// Scratch
__device__ float g_agg[MAXN * D];      // segment_sum target
__device__ float g_P[MAXN * 384];      // [0:128]=nf@We1_s, [128:256]=nf@We1_r, [256:384]=nf@Wn1_n

typedef unsigned int u32;
typedef unsigned long long u64;

extern __shared__ char smem_raw[];

// ---- edge/node kernel smem map (per CTA, 64-row tiles, 256 threads) ----
//   0:    sSS[64] (256B), 256: sSR[64] (256B)
//   512:  A hi  (64 x 72 bf16  =  9216)
//   9728: A lo  (9216)
//   18944:H hi  (64 x 136 bf16 = 17408)
//   36352:H lo  (17408)
//   53760:W2t hi(64 x 136 bf16 = 17408)
//   71168:W2t lo(17408)            -> total 88576
//   sF fp32 [64][68] = 17408 overlays A @512
#define EOFF_AH   512
#define EOFF_AL   9728
#define EOFF_HH   18944
#define EOFF_HL   36352
#define EOFF_W2H  53760
#define EOFF_W2L  71168
#define EDGE_SMEM 88576

// ---- pproj smem map (128-row tile, 512 threads) ----
#define POFF_AH   1024
#define POFF_AL   19456
#define PPROJ_SMEM 37888

// ============================================================================
__device__ __forceinline__ u32 smem_u32(const void* p) {
    u32 a; asm("{ .reg .u64 t; cvta.to.shared.u64 t, %1; cvt.u32.u64 %0, t; }" : "=r"(a) : "l"(p));
    return a;
}
// pack two fp32 -> bf16x2 {low=lo, high=hi}
__device__ __forceinline__ u32 pack_bf2(float lo, float hi) {
    u32 r; asm("cvt.rn.bf16x2.f32 %0, %1, %2;" : "=r"(r) : "f"(hi), "f"(lo)); return r;
}
__device__ __forceinline__ float lowf(u32 p)  { return __uint_as_float(p << 16); }
__device__ __forceinline__ float highf(u32 p) { return __uint_as_float(p & 0xFFFF0000u); }

__device__ __forceinline__ void ldsm4(u32* r, u32 addr) {
    asm volatile("ldmatrix.sync.aligned.m8n8.x4.shared.b16 {%0,%1,%2,%3}, [%4];"
        : "=r"(r[0]), "=r"(r[1]), "=r"(r[2]), "=r"(r[3]) : "r"(addr));
}
__device__ __forceinline__ void ldsm2(u32* r, u32 addr) {
    asm volatile("ldmatrix.sync.aligned.m8n8.x2.shared.b16 {%0,%1}, [%2];"
        : "=r"(r[0]), "=r"(r[1]) : "r"(addr));
}
__device__ __forceinline__ void mma_bf(float* c, const u32* a, const u32* b) {
    asm volatile("mma.sync.aligned.m16n8k16.row.col.f32.bf16.bf16.f32 "
        "{%0,%1,%2,%3}, {%4,%5,%6,%7}, {%8,%9}, {%0,%1,%2,%3};"
        : "+f"(c[0]), "+f"(c[1]), "+f"(c[2]), "+f"(c[3])
        : "r"(a[0]), "r"(a[1]), "r"(a[2]), "r"(a[3]), "r"(b[0]), "r"(b[1]));
}
__device__ __forceinline__ void build_frag(const float* __restrict__ W, int ldw,
                                           int n, int k0, u32& hi, u32& lo) {
    const float w0 = W[k0 * ldw + n];
    const float w1 = W[(k0 + 1) * ldw + n];
    hi = pack_bf2(w0, w1);
    lo = pack_bf2(w0 - lowf(hi), w1 - highf(hi));
}
// stage one quarter-row (16 floats) as bf16 hi/lo into A buffers at offH/offL
__device__ __forceinline__ void stage_row_quarter(char* sm, const float4* src4,
                                                  int row, int q, int offH, int offL) {
#pragma unroll
    for (int j = 0; j < 4; j++) {
        const float4 v = src4[q + 4 * j];
        const int col = (q + 4 * j) * 4;
        const u32 off = (u32)(row * SA_STRIDE + col) * 2;
        const u32 h0 = pack_bf2(v.x, v.y);
        const u32 h1 = pack_bf2(v.z, v.w);
        *(u32*)(sm + offH + off)     = h0;
        *(u32*)(sm + offH + off + 4) = h1;
        *(u32*)(sm + offL + off)     = pack_bf2(v.x - lowf(h0), v.y - highf(h0));
        *(u32*)(sm + offL + off + 4) = pack_bf2(v.z - lowf(h1), v.w - highf(h1));
    }
}
// stage transposed W2 (64n x 128k) bf16 hi/lo into smem (once per CTA)
__device__ __forceinline__ void stage_w2t(char* sm, const float* __restrict__ W2, int tid) {
    for (int i = tid; i < 64 * 64; i += 256) {
        const int n = i >> 6, kp = i & 63;
        const float w0 = W2[(2 * kp) * 64 + n];
        const float w1 = W2[(2 * kp + 1) * 64 + n];
        const u32 hi = pack_bf2(w0, w1);
        const u32 lo = pack_bf2(w0 - lowf(hi), w1 - highf(hi));
        const u32 off = (u32)(n * SH_STRIDE + 2 * kp) * 2;
        *(u32*)(sm + EOFF_W2H + off) = hi;
        *(u32*)(sm + EOFF_W2L + off) = lo;
    }
}

// ============================================================================
__global__ void zero_agg_kernel(int n4) {
    int i = blockIdx.x * blockDim.x + threadIdx.x;
    if (i < n4) reinterpret_cast<float4*>(g_agg)[i] = make_float4(0.f, 0.f, 0.f, 0.f);
}

// ============================================================================
// P projection (mma bf16 3-term): g_P[n][seg*128+c] for seg in {We1_s, We1_r, Wn1_n}
__global__ __launch_bounds__(512)
void pproj_kernel(const float* __restrict__ nodef,
                  const float* __restrict__ We1, const float* __restrict__ Wn1, int N)
{
    char* sm = smem_raw;
    const u32 smb = smem_u32(sm);
    const u32 ahb = smb + POFF_AH, alb = smb + POFF_AL;

    const int tid = threadIdx.x, wid = tid >> 5, lid = tid & 31;
    const int nrow = lid >> 2, cq = (lid & 3) * 2;
    const int base = blockIdx.x * 128;

    u32 bh[3][4][2], bl[3][4][2];
    {
        const int n = wid * 8 + nrow;
#pragma unroll
        for (int kt = 0; kt < 4; kt++)
#pragma unroll
            for (int r = 0; r < 2; r++) {
                const int k = kt * 16 + cq + r * 8;
                build_frag(We1 + (size_t)64 * 128, 128, n, k, bh[0][kt][r], bl[0][kt][r]);
                build_frag(We1 + (size_t)128 * 128, 128, n, k, bh[1][kt][r], bl[1][kt][r]);
                build_frag(Wn1 + (size_t)64 * 128, 128, n, k, bh[2][kt][r], bl[2][kt][r]);
            }
    }
    {
        const int row = tid >> 2, q = tid & 3;
        int g = base + row; if (g >= N) g = N - 1;
        stage_row_quarter(sm, (const float4*)(nodef + (size_t)g * 64), row, q, POFF_AH, POFF_AL);
    }
    __syncthreads();

    const int trow = (lid & 7) + ((lid >> 3) & 1) * 8;
    const int tcol = (lid >> 4) * 8;
    const u32 offA = (u32)(trow * SA_STRIDE + tcol) * 2;
    const int n0 = wid * 8 + cq;

#pragma unroll
    for (int mt = 0; mt < 8; mt++) {
        u32 ah[4][4], al[4][4];
        const u32 bhA = ahb + offA + mt * (16 * SA_STRIDE * 2);
        const u32 blA = alb + offA + mt * (16 * SA_STRIDE * 2);
#pragma unroll
        for (int kt = 0; kt < 4; kt++) {
            ldsm4(ah[kt], bhA + kt * 32);
            ldsm4(al[kt], blA + kt * 32);
        }
        const int g0 = base + mt * 16 + nrow, g1 = g0 + 8;
#pragma unroll
        for (int seg = 0; seg < 3; seg++) {
            float acc[4] = {0.f, 0.f, 0.f, 0.f};
#pragma unroll
            for (int kt = 0; kt < 4; kt++) {
                mma_bf(acc, ah[kt], bh[seg][kt]);
                mma_bf(acc, ah[kt], bl[seg][kt]);
                mma_bf(acc, al[kt], bh[seg][kt]);
            }
            if (g0 < N) *(float2*)(g_P + (size_t)g0 * 384 + seg * 128 + n0) =
                            make_float2(acc[0], acc[1]);
            if (g1 < N) *(float2*)(g_P + (size_t)g1 * 384 + seg * 128 + n0) =
                            make_float2(acc[2], acc[3]);
        }
    }
}

// ============================================================================
// Edge kernel: persistent, 256 threads, 2 CTAs/SM, 64-edge tiles.
__global__ __launch_bounds__(256, 2)
void edge_kernel(const float* __restrict__ edgef,
                 const float* __restrict__ We1, const float* __restrict__ be1,
                 const float* __restrict__ We2, const float* __restrict__ be2,
                 const int* __restrict__ senders, const int* __restrict__ recvs,
                 float* __restrict__ e_out, int E)
{
    char* sm = smem_raw;
    int* sSS = (int*)sm;
    int* sSR = (int*)(sm + 256);
    float* sF = (float*)(sm + EOFF_AH);       // epilogue2 fp32 staging [64][68]
    const u32 smb = smem_u32(sm);
    const u32 ahb = smb + EOFF_AH, alb = smb + EOFF_AL;
    const u32 hhb = smb + EOFF_HH, hlb = smb + EOFF_HL;
    const u32 w2h = smb + EOFF_W2H, w2l = smb + EOFF_W2L;

    const int tid = threadIdx.x, wid = tid >> 5, lid = tid & 31;
    const int nrow = lid >> 2, cq = (lid & 3) * 2;

    // ---- stage W2^T (bf16 hi/lo) once per CTA ----
    stage_w2t(sm, We2, tid);

    // ---- layer-1 weight fragments in registers (2 n-blocks per warp) ----
    u32 b1h[2][4][2], b1l[2][4][2];
#pragma unroll
    for (int nt = 0; nt < 2; nt++) {
        const int n = wid * 16 + nt * 8 + nrow;
#pragma unroll
        for (int kt = 0; kt < 4; kt++)
#pragma unroll
            for (int r = 0; r < 2; r++)
                build_frag(We1, 128, n, kt * 16 + cq + r * 8, b1h[nt][kt][r], b1l[nt][kt][r]);
    }
    float2 bb1[2];
    bb1[0] = *(const float2*)(be1 + wid * 16 + cq);
    bb1[1] = *(const float2*)(be1 + wid * 16 + 8 + cq);
    const float2 bb2 = *(const float2*)(be2 + wid * 8 + cq);

    const int trow = (lid & 7) + ((lid >> 3) & 1) * 8;
    const int tcol = (lid >> 4) * 8;
    const u32 offA = (u32)(trow * SA_STRIDE + tcol) * 2;
    const u32 offH = (u32)(trow * SH_STRIDE + tcol) * 2;
    // B-frag ldmatrix.x2 address (layer2): rows n = wid*8 + (lid&7), col block by lid bit3
    const u32 offB = (u32)((wid * 8 + (lid & 7)) * SH_STRIDE + ((lid >> 3) & 1) * 8) * 2;

    const int nTiles = (E + 63) / 64;

    for (int tile = blockIdx.x; tile < nTiles; tile += gridDim.x) {
        const int base = tile * 64;
        __syncthreads();

        // ---- stage indices + A ----
        if (tid < 64) {
            int g = base + tid; if (g >= E) g = E - 1;
            sSS[tid] = senders[g];
            sSR[tid] = recvs[g];
        }
        {
            const int row = tid >> 2, q = tid & 3;
            int ge = base + row; if (ge >= E) ge = E - 1;
            stage_row_quarter(sm, (const float4*)(edgef + (size_t)ge * 64), row, q, EOFF_AH, EOFF_AL);
        }
        __syncthreads();

        // ---- layer 1: acc1[64,128] = A @ We1_e^T (+be1) ----
        float acc1[4][2][4];
#pragma unroll
        for (int mt = 0; mt < 4; mt++)
#pragma unroll
            for (int nt = 0; nt < 2; nt++) {
                acc1[mt][nt][0] = bb1[nt].x; acc1[mt][nt][1] = bb1[nt].y;
                acc1[mt][nt][2] = bb1[nt].x; acc1[mt][nt][3] = bb1[nt].y;
            }
#pragma unroll
        for (int mt = 0; mt < 4; mt++) {
            const u32 bh = ahb + offA + mt * (16 * SA_STRIDE * 2);
            const u32 bl = alb + offA + mt * (16 * SA_STRIDE * 2);
#pragma unroll
            for (int kt = 0; kt < 4; kt++) {
                u32 ah[4], al[4];
                ldsm4(ah, bh + kt * 32);
                ldsm4(al, bl + kt * 32);
#pragma unroll
                for (int nt = 0; nt < 2; nt++) {
                    mma_bf(acc1[mt][nt], ah, b1h[nt][kt]);
                    mma_bf(acc1[mt][nt], ah, b1l[nt][kt]);
                    mma_bf(acc1[mt][nt], al, b1h[nt][kt]);
                }
            }
        }

        // ---- epilogue1: h = relu(acc1 + P1[s] + P2[r]) -> H smem bf16 hi/lo ----
#pragma unroll
        for (int nt = 0; nt < 2; nt++) {
            const int n0 = wid * 16 + nt * 8 + cq;
            float2 p1a[4], p2a[4], p1b[4], p2b[4];
#pragma unroll
            for (int mt = 0; mt < 4; mt++) {
                const int m0 = mt * 16 + nrow, m1 = m0 + 8;
                p1a[mt] = __ldg((const float2*)(g_P + (size_t)sSS[m0] * 384 + n0));
                p2a[mt] = __ldg((const float2*)(g_P + (size_t)sSR[m0] * 384 + 128 + n0));
                p1b[mt] = __ldg((const float2*)(g_P + (size_t)sSS[m1] * 384 + n0));
                p2b[mt] = __ldg((const float2*)(g_P + (size_t)sSR[m1] * 384 + 128 + n0));
            }
#pragma unroll
            for (int mt = 0; mt < 4; mt++) {
                const int m0 = mt * 16 + nrow, m1 = m0 + 8;
                const float x0 = fmaxf(acc1[mt][nt][0] + p1a[mt].x + p2a[mt].x, 0.f);
                const float x1 = fmaxf(acc1[mt][nt][1] + p1a[mt].y + p2a[mt].y, 0.f);
                const float x2 = fmaxf(acc1[mt][nt][2] + p1b[mt].x + p2b[mt].x, 0.f);
                const float x3 = fmaxf(acc1[mt][nt][3] + p1b[mt].y + p2b[mt].y, 0.f);
                const u32 h0 = pack_bf2(x0, x1);
                const u32 h1 = pack_bf2(x2, x3);
                *(u32*)(sm + EOFF_HH + (m0 * SH_STRIDE + n0) * 2) = h0;
                *(u32*)(sm + EOFF_HH + (m1 * SH_STRIDE + n0) * 2) = h1;
                *(u32*)(sm + EOFF_HL + (m0 * SH_STRIDE + n0) * 2) =
                    pack_bf2(x0 - lowf(h0), x1 - highf(h0));
                *(u32*)(sm + EOFF_HL + (m1 * SH_STRIDE + n0) * 2) =
                    pack_bf2(x2 - lowf(h1), x3 - highf(h1));
            }
        }
        __syncthreads();

        // ---- layer 2: acc2[64,64] = h @ We2^T (+be2); B frags via ldmatrix ----
        float acc2[4][4];
#pragma unroll
        for (int mt = 0; mt < 4; mt++) {
            acc2[mt][0] = bb2.x; acc2[mt][1] = bb2.y;
            acc2[mt][2] = bb2.x; acc2[mt][3] = bb2.y;
        }
#pragma unroll
        for (int kt = 0; kt < 8; kt++) {
            u32 bfh[2], bfl[2];
            ldsm2(bfh, w2h + offB + kt * 32);
            ldsm2(bfl, w2l + offB + kt * 32);
#pragma unroll
            for (int mt = 0; mt < 4; mt++) {
                u32 ah[4], al[4];
                const u32 rb = mt * (16 * SH_STRIDE * 2) + kt * 32;
                ldsm4(ah, hhb + offH + rb);
                ldsm4(al, hlb + offH + rb);
                mma_bf(acc2[mt], ah, bfh);
                mma_bf(acc2[mt], ah, bfl);
                mma_bf(acc2[mt], al, bfh);
            }
        }

        // ---- epilogue2: stage fp32 -> float4 stores + atomics ----
        {
            const int n2 = wid * 8 + cq;
#pragma unroll
            for (int mt = 0; mt < 4; mt++) {
                const int m0 = mt * 16 + nrow, m1 = m0 + 8;
                *(float2*)(sF + m0 * 68 + n2) = make_float2(acc2[mt][0], acc2[mt][1]);
                *(float2*)(sF + m1 * 68 + n2) = make_float2(acc2[mt][2], acc2[mt][3]);
            }
        }
        __syncthreads();
        {
            const int row = tid >> 2, q = tid & 3;
            const int ge = base + row;
            if (ge < E) {
                const int ridx = sSR[row];
#pragma unroll
                for (int j = 0; j < 4; j++) {
                    const int col = (q + 4 * j) * 4;
                    const float4 v = *(const float4*)(sF + row * 68 + col);
                    *(float4*)(e_out + (size_t)ge * 64 + col) = v;
                    atomicAdd((float4*)(g_agg + (size_t)ridx * 64 + col), v);
                }
            }
        }
    }
}

// ============================================================================
// Node kernel: n = relu(agg@Wn1_a + Q[node] + bn1) @ Wn2 + bn2
__global__ __launch_bounds__(256, 2)
void node_kernel(const float* __restrict__ Wn1, const float* __restrict__ bn1,
                 const float* __restrict__ Wn2, const float* __restrict__ bn2,
                 float* __restrict__ n_out, int N)
{
    char* sm = smem_raw;
    const u32 smb = smem_u32(sm);
    const u32 ahb = smb + EOFF_AH, alb = smb + EOFF_AL;
    const u32 hhb = smb + EOFF_HH, hlb = smb + EOFF_HL;
    const u32 w2h = smb + EOFF_W2H, w2l = smb + EOFF_W2L;

    const int tid = threadIdx.x, wid = tid >> 5, lid = tid & 31;
    const int nrow = lid >> 2, cq = (lid & 3) * 2;
    const int base = blockIdx.x * 64;

    stage_w2t(sm, Wn2, tid);

    u32 b1h[2][4][2], b1l[2][4][2];
#pragma unroll
    for (int nt = 0; nt < 2; nt++) {
        const int n = wid * 16 + nt * 8 + nrow;
#pragma unroll
        for (int kt = 0; kt < 4; kt++)
#pragma unroll
            for (int r = 0; r < 2; r++)
                build_frag(Wn1, 128, n, kt * 16 + cq + r * 8, b1h[nt][kt][r], b1l[nt][kt][r]);
    }
    float2 bb1[2];
    bb1[0] = *(const float2*)(bn1 + wid * 16 + cq);
    bb1[1] = *(const float2*)(bn1 + wid * 16 + 8 + cq);
    const float2 bb2 = *(const float2*)(bn2 + wid * 8 + cq);

    const int trow = (lid & 7) + ((lid >> 3) & 1) * 8;
    const int tcol = (lid >> 4) * 8;
    const u32 offA = (u32)(trow * SA_STRIDE + tcol) * 2;
    const u32 offH = (u32)(trow * SH_STRIDE + tcol) * 2;
    const u32 offB = (u32)((wid * 8 + (lid & 7)) * SH_STRIDE + ((lid >> 3) & 1) * 8) * 2;

    // stage A = agg tile
    {
        const int row = tid >> 2, q = tid & 3;
        int g = base + row; if (g >= N) g = N - 1;
        stage_row_quarter(sm, (const float4*)(g_agg + (size_t)g * 64), row, q, EOFF_AH, EOFF_AL);
    }
    __syncthreads();

    // layer 1
    float acc1[4][2][4];
#pragma unroll
    for (int mt = 0; mt < 4; mt++)
#pragma unroll
        for (int nt = 0; nt < 2; nt++) {
            acc1[mt][nt][0] = bb1[nt].x; acc1[mt][nt][1] = bb1[nt].y;
            acc1[mt][nt][2] = bb1[nt].x; acc1[mt][nt][3] = bb1[nt].y;
        }
#pragma unroll
    for (int mt = 0; mt < 4; mt++) {
        const u32 bh = ahb + offA + mt * (16 * SA_STRIDE * 2);
        const u32 bl = alb + offA + mt * (16 * SA_STRIDE * 2);
#pragma unroll
        for (int kt = 0; kt < 4; kt++) {
            u32 ah[4], al[4];
            ldsm4(ah, bh + kt * 32);
            ldsm4(al, bl + kt * 32);
#pragma unroll
            for (int nt = 0; nt < 2; nt++) {
                mma_bf(acc1[mt][nt], ah, b1h[nt][kt]);
                mma_bf(acc1[mt][nt], ah, b1l[nt][kt]);
                mma_bf(acc1[mt][nt], al, b1h[nt][kt]);
            }
        }
    }

    // epilogue1: h = relu(acc1 + Q[node])
#pragma unroll
    for (int nt = 0; nt < 2; nt++) {
        const int n0 = wid * 16 + nt * 8 + cq;
#pragma unroll
        for (int mt = 0; mt < 4; mt++) {
            const int m0 = mt * 16 + nrow, m1 = m0 + 8;
            int g0 = base + m0; if (g0 >= N) g0 = N - 1;
            int g1 = base + m1; if (g1 >= N) g1 = N - 1;
            const float2 qa = __ldg((const float2*)(g_P + (size_t)g0 * 384 + 256 + n0));
            const float2 qb = __ldg((const float2*)(g_P + (size_t)g1 * 384 + 256 + n0));
            const float x0 = fmaxf(acc1[mt][nt][0] + qa.x, 0.f);
            const float x1 = fmaxf(acc1[mt][nt][1] + qa.y, 0.f);
            const float x2 = fmaxf(acc1[mt][nt][2] + qb.x, 0.f);
            const float x3 = fmaxf(acc1[mt][nt][3] + qb.y, 0.f);
            const u32 h0 = pack_bf2(x0, x1);
            const u32 h1 = pack_bf2(x2, x3);
            *(u32*)(sm + EOFF_HH + (m0 * SH_STRIDE + n0) * 2) = h0;
            *(u32*)(sm + EOFF_HH + (m1 * SH_STRIDE + n0) * 2) = h1;
            *(u32*)(sm + EOFF_HL + (m0 * SH_STRIDE + n0) * 2) =
                pack_bf2(x0 - lowf(h0), x1 - highf(h0));
            *(u32*)(sm + EOFF_HL + (m1 * SH_STRIDE + n0) * 2) =
                pack_bf2(x2 - lowf(h1), x3 - highf(h1));
        }
    }
    __syncthreads();

    // layer 2
    float acc2[4][4];
#pragma unroll
    for (int mt = 0; mt < 4; mt++) {
        acc2[mt][0] = bb2.x; acc2[mt][1] = bb2.y;
        acc2[mt][2] = bb2.x; acc2[mt][3] = bb2.y;
    }
#pragma unroll
    for (int kt = 0; kt < 8; kt++) {
        u32 bfh[2], bfl[2];
        ldsm2(bfh, w2h + offB + kt * 32);
        ldsm2(bfl, w2l + offB + kt * 32);
#pragma unroll
        for (int mt = 0; mt < 4; mt++) {
            u32 ah[4], al[4];
            const u32 rb = mt * (16 * SH_STRIDE * 2) + kt * 32;
            ldsm4(ah, hhb + offH + rb);
            ldsm4(al, hlb + offH + rb);
            mma_bf(acc2[mt], ah, bfh);
            mma_bf(acc2[mt], ah, bfl);
            mma_bf(acc2[mt], al, bfh);
        }
    }

    // epilogue2: direct stores
    {
        const int n2 = wid * 8 + cq;
#pragma unroll
        for (int mt = 0; mt < 4; mt++) {
            const int m0 = mt * 16 + nrow, m1 = m0 + 8;
            const int g0 = base + m0, g1 = base + m1;
            if (g0 < N) *(float2*)(n_out + (size_t)g0 * 64 + n2) =
                            make_float2(acc2[mt][0], acc2[mt][1]);
            if (g1 < N) *(float2*)(n_out + (size_t)g1 * 64 + n2) =
                            make_float2(acc2[mt][2], acc2[mt][3]);
        }
    }
}

// ============================================================================
extern "C" void kernel_launch(void* const* d_in, const int* in_sizes, int n_in,
                              void* d_out, int out_size)
{
    const float* node_feats = (const float*)d_in[0];
    const float* edge_feats = (const float*)d_in[1];
    const float* We1 = (const float*)d_in[2];
    const float* be1 = (const float*)d_in[3];
    const float* We2 = (const float*)d_in[4];
    const float* be2 = (const float*)d_in[5];
    const float* Wn1 = (const float*)d_in[6];
    const float* bn1 = (const float*)d_in[7];
    const float* Wn2 = (const float*)d_in[8];
    const float* bn2 = (const float*)d_in[9];
    const int* senders   = (const int*)d_in[10];
    const int* receivers = (const int*)d_in[11];

    const int N = in_sizes[0] / D;
    const int E = in_sizes[1] / D;

    float* out   = (float*)d_out;
    float* e_out = out;                   // [E, D]
    float* n_out = out + (size_t)E * D;   // [N, D]

    cudaFuncSetAttribute(pproj_kernel, cudaFuncAttributeMaxDynamicSharedMemorySize, PPROJ_SMEM);
    cudaFuncSetAttribute(edge_kernel,  cudaFuncAttributeMaxDynamicSharedMemorySize, EDGE_SMEM);
    cudaFuncSetAttribute(node_kernel,  cudaFuncAttributeMaxDynamicSharedMemorySize, EDGE_SMEM);

    int dev = 0, sms = 148;
    cudaGetDevice(&dev);
    cudaDeviceGetAttribute(&sms, cudaDevAttrMultiProcessorCount, dev);

    const int n4 = N * D / 4;
    zero_agg_kernel<<<(n4 + 255) / 256, 256>>>(n4);

    pproj_kernel<<<(N + 127) / 128, 512, PPROJ_SMEM>>>(node_feats, We1, Wn1, N);

    edge_kernel<<<2 * sms, 256, EDGE_SMEM>>>(edge_feats, We1, be1, We2, be2,
                                             senders, receivers, e_out, E);

    node_kernel<<<(N + 63) / 64, 256, EDGE_SMEM>>>(Wn1, bn1, Wn2, bn2, n_out, N);
}

// round 10
// speedup vs baseline: 3.7684x; 1.0135x over previous
#include <cuda_runtime.h>
#include <cuda_bf16.h>

// Problem constants (fixed dataset: N=50000, E=800000, D=64, H=128)
#define D  64
#define H  128
#define MAXN 50000

#define SA_STRIDE 72     // bf16 elems per row (64 + 8 pad)
#define SH_STRIDE 136    // bf16 elems per row (128 + 8 pad)

// Scratch
__device__ float g_agg[MAXN * D];      // segment_sum target
__device__ float g_P[MAXN * 384];      // [0:128]=nf@We1_s, [128:256]=nf@We1_r, [256:384]=nf@Wn1_n

typedef unsigned int u32;
typedef unsigned long long u64;

extern __shared__ char smem_raw[];

// ---- edge kernel smem map (64-row tiles, 256 threads, 2 CTAs/SM) ----
#define EOFF_AH   512
#define EOFF_AL   9728
#define EOFF_HH   18944
#define EOFF_HL   36352
#define EOFF_W2H  53760
#define EOFF_W2L  71168
#define EDGE_SMEM 88576

// ---- node/pproj smem map (128-row tiles, 512 threads, 1 CTA/SM) ----
#define BOFF_AH   1024
#define BOFF_AL   19456
#define BOFF_HH   37888
#define BOFF_HL   72704
#define BIG_SMEM  107520
#define PPROJ_SMEM 37888

// ============================================================================
__device__ __forceinline__ u32 smem_u32(const void* p) {
    u32 a; asm("{ .reg .u64 t; cvta.to.shared.u64 t, %1; cvt.u32.u64 %0, t; }" : "=r"(a) : "l"(p));
    return a;
}
__device__ __forceinline__ u32 pack_bf2(float lo, float hi) {
    u32 r; asm("cvt.rn.bf16x2.f32 %0, %1, %2;" : "=r"(r) : "f"(hi), "f"(lo)); return r;
}
__device__ __forceinline__ float lowf(u32 p)  { return __uint_as_float(p << 16); }
__device__ __forceinline__ float highf(u32 p) { return __uint_as_float(p & 0xFFFF0000u); }

__device__ __forceinline__ void ldsm4(u32* r, u32 addr) {
    asm volatile("ldmatrix.sync.aligned.m8n8.x4.shared.b16 {%0,%1,%2,%3}, [%4];"
        : "=r"(r[0]), "=r"(r[1]), "=r"(r[2]), "=r"(r[3]) : "r"(addr));
}
__device__ __forceinline__ void ldsm2(u32* r, u32 addr) {
    asm volatile("ldmatrix.sync.aligned.m8n8.x2.shared.b16 {%0,%1}, [%2];"
        : "=r"(r[0]), "=r"(r[1]) : "r"(addr));
}
__device__ __forceinline__ void mma_bf(float* c, const u32* a, const u32* b) {
    asm volatile("mma.sync.aligned.m16n8k16.row.col.f32.bf16.bf16.f32 "
        "{%0,%1,%2,%3}, {%4,%5,%6,%7}, {%8,%9}, {%0,%1,%2,%3};"
        : "+f"(c[0]), "+f"(c[1]), "+f"(c[2]), "+f"(c[3])
        : "r"(a[0]), "r"(a[1]), "r"(a[2]), "r"(a[3]), "r"(b[0]), "r"(b[1]));
}
__device__ __forceinline__ void build_frag(const float* __restrict__ W, int ldw,
                                           int n, int k0, u32& hi, u32& lo) {
    const float w0 = W[k0 * ldw + n];
    const float w1 = W[(k0 + 1) * ldw + n];
    hi = pack_bf2(w0, w1);
    lo = pack_bf2(w0 - lowf(hi), w1 - highf(hi));
}
__device__ __forceinline__ void stage_row_quarter(char* sm, const float4* src4,
                                                  int row, int q, int offH, int offL) {
#pragma unroll
    for (int j = 0; j < 4; j++) {
        const float4 v = src4[q + 4 * j];
        const int col = (q + 4 * j) * 4;
        const u32 off = (u32)(row * SA_STRIDE + col) * 2;
        const u32 h0 = pack_bf2(v.x, v.y);
        const u32 h1 = pack_bf2(v.z, v.w);
        *(u32*)(sm + offH + off)     = h0;
        *(u32*)(sm + offH + off + 4) = h1;
        *(u32*)(sm + offL + off)     = pack_bf2(v.x - lowf(h0), v.y - highf(h0));
        *(u32*)(sm + offL + off + 4) = pack_bf2(v.z - lowf(h1), v.w - highf(h1));
    }
}
// stage transposed W2 (64n x 128k) bf16 hi/lo into smem (edge kernel, 256 thr)
__device__ __forceinline__ void stage_w2t(char* sm, const float* __restrict__ W2, int tid) {
    for (int i = tid; i < 64 * 64; i += 256) {
        const int n = i >> 6, kp = i & 63;
        const float w0 = W2[(2 * kp) * 64 + n];
        const float w1 = W2[(2 * kp + 1) * 64 + n];
        const u32 hi = pack_bf2(w0, w1);
        const u32 lo = pack_bf2(w0 - lowf(hi), w1 - highf(hi));
        const u32 off = (u32)(n * SH_STRIDE + 2 * kp) * 2;
        *(u32*)(sm + EOFF_W2H + off) = hi;
        *(u32*)(sm + EOFF_W2L + off) = lo;
    }
}

// ============================================================================
__global__ void zero_agg_kernel(int n4) {
    int i = blockIdx.x * blockDim.x + threadIdx.x;
    if (i < n4) reinterpret_cast<float4*>(g_agg)[i] = make_float4(0.f, 0.f, 0.f, 0.f);
}

// ============================================================================
// P projection (mma bf16 3-term): g_P[n][seg*128+c] for seg in {We1_s, We1_r, Wn1_n}
__global__ __launch_bounds__(512)
void pproj_kernel(const float* __restrict__ nodef,
                  const float* __restrict__ We1, const float* __restrict__ Wn1, int N)
{
    char* sm = smem_raw;
    const u32 smb = smem_u32(sm);
    const u32 ahb = smb + BOFF_AH, alb = smb + BOFF_AL;

    const int tid = threadIdx.x, wid = tid >> 5, lid = tid & 31;
    const int nrow = lid >> 2, cq = (lid & 3) * 2;
    const int base = blockIdx.x * 128;

    u32 bh[3][4][2], bl[3][4][2];
    {
        const int n = wid * 8 + nrow;
#pragma unroll
        for (int kt = 0; kt < 4; kt++)
#pragma unroll
            for (int r = 0; r < 2; r++) {
                const int k = kt * 16 + cq + r * 8;
                build_frag(We1 + (size_t)64 * 128, 128, n, k, bh[0][kt][r], bl[0][kt][r]);
                build_frag(We1 + (size_t)128 * 128, 128, n, k, bh[1][kt][r], bl[1][kt][r]);
                build_frag(Wn1 + (size_t)64 * 128, 128, n, k, bh[2][kt][r], bl[2][kt][r]);
            }
    }
    {
        const int row = tid >> 2, q = tid & 3;
        int g = base + row; if (g >= N) g = N - 1;
        stage_row_quarter(sm, (const float4*)(nodef + (size_t)g * 64), row, q, BOFF_AH, BOFF_AL);
    }
    __syncthreads();

    const int trow = (lid & 7) + ((lid >> 3) & 1) * 8;
    const int tcol = (lid >> 4) * 8;
    const u32 offA = (u32)(trow * SA_STRIDE + tcol) * 2;
    const int n0 = wid * 8 + cq;

#pragma unroll
    for (int mt = 0; mt < 8; mt++) {
        u32 ah[4][4], al[4][4];
        const u32 bhA = ahb + offA + mt * (16 * SA_STRIDE * 2);
        const u32 blA = alb + offA + mt * (16 * SA_STRIDE * 2);
#pragma unroll
        for (int kt = 0; kt < 4; kt++) {
            ldsm4(ah[kt], bhA + kt * 32);
            ldsm4(al[kt], blA + kt * 32);
        }
        const int g0 = base + mt * 16 + nrow, g1 = g0 + 8;
#pragma unroll
        for (int seg = 0; seg < 3; seg++) {
            float acc[4] = {0.f, 0.f, 0.f, 0.f};
#pragma unroll
            for (int kt = 0; kt < 4; kt++) {
                mma_bf(acc, ah[kt], bh[seg][kt]);
                mma_bf(acc, ah[kt], bl[seg][kt]);
                mma_bf(acc, al[kt], bh[seg][kt]);
            }
            if (g0 < N) *(float2*)(g_P + (size_t)g0 * 384 + seg * 128 + n0) =
                            make_float2(acc[0], acc[1]);
            if (g1 < N) *(float2*)(g_P + (size_t)g1 * 384 + seg * 128 + n0) =
                            make_float2(acc[2], acc[3]);
        }
    }
}

// ============================================================================
// Edge kernel: persistent, 256 threads, 2 CTAs/SM, 64-edge tiles, P prefetch.
__global__ __launch_bounds__(256, 2)
void edge_kernel(const float* __restrict__ edgef,
                 const float* __restrict__ We1, const float* __restrict__ be1,
                 const float* __restrict__ We2, const float* __restrict__ be2,
                 const int* __restrict__ senders, const int* __restrict__ recvs,
                 float* __restrict__ e_out, int E)
{
    char* sm = smem_raw;
    int* sSS = (int*)sm;
    int* sSR = (int*)(sm + 256);
    float* sF = (float*)(sm + EOFF_AH);       // epilogue2 fp32 staging [64][68]
    const u32 smb = smem_u32(sm);
    const u32 ahb = smb + EOFF_AH, alb = smb + EOFF_AL;
    const u32 hhb = smb + EOFF_HH, hlb = smb + EOFF_HL;
    const u32 w2h = smb + EOFF_W2H, w2l = smb + EOFF_W2L;

    const int tid = threadIdx.x, wid = tid >> 5, lid = tid & 31;
    const int nrow = lid >> 2, cq = (lid & 3) * 2;

    stage_w2t(sm, We2, tid);

    u32 b1h[2][4][2], b1l[2][4][2];
#pragma unroll
    for (int nt = 0; nt < 2; nt++) {
        const int n = wid * 16 + nt * 8 + nrow;
#pragma unroll
        for (int kt = 0; kt < 4; kt++)
#pragma unroll
            for (int r = 0; r < 2; r++)
                build_frag(We1, 128, n, kt * 16 + cq + r * 8, b1h[nt][kt][r], b1l[nt][kt][r]);
    }
    float2 bb1[2];
    bb1[0] = *(const float2*)(be1 + wid * 16 + cq);
    bb1[1] = *(const float2*)(be1 + wid * 16 + 8 + cq);
    const float2 bb2 = *(const float2*)(be2 + wid * 8 + cq);

    const int trow = (lid & 7) + ((lid >> 3) & 1) * 8;
    const int tcol = (lid >> 4) * 8;
    const u32 offA = (u32)(trow * SA_STRIDE + tcol) * 2;
    const u32 offH = (u32)(trow * SH_STRIDE + tcol) * 2;
    const u32 offB = (u32)((wid * 8 + (lid & 7)) * SH_STRIDE + ((lid >> 3) & 1) * 8) * 2;

    const int nTiles = (E + 63) / 64;

    for (int tile = blockIdx.x; tile < nTiles; tile += gridDim.x) {
        const int base = tile * 64;
        __syncthreads();

        // ---- stage indices + A ----
        if (tid < 64) {
            int g = base + tid; if (g >= E) g = E - 1;
            sSS[tid] = senders[g];
            sSR[tid] = recvs[g];
        }
        {
            const int row = tid >> 2, q = tid & 3;
            int ge = base + row; if (ge >= E) ge = E - 1;
            stage_row_quarter(sm, (const float4*)(edgef + (size_t)ge * 64), row, q, EOFF_AH, EOFF_AL);
        }
        __syncthreads();

        // ---- prefetch P1[s]+P2[r] (summed) BEFORE MMA1 so L2 latency hides ----
        float2 psum[2][4][2];   // [nt][mt][row0/1]
#pragma unroll
        for (int nt = 0; nt < 2; nt++) {
            const int n0 = wid * 16 + nt * 8 + cq;
#pragma unroll
            for (int mt = 0; mt < 4; mt++) {
                const int m0 = mt * 16 + nrow, m1 = m0 + 8;
                const float2 a = __ldg((const float2*)(g_P + (size_t)sSS[m0] * 384 + n0));
                const float2 b = __ldg((const float2*)(g_P + (size_t)sSR[m0] * 384 + 128 + n0));
                const float2 c = __ldg((const float2*)(g_P + (size_t)sSS[m1] * 384 + n0));
                const float2 d = __ldg((const float2*)(g_P + (size_t)sSR[m1] * 384 + 128 + n0));
                psum[nt][mt][0] = make_float2(a.x + b.x, a.y + b.y);
                psum[nt][mt][1] = make_float2(c.x + d.x, c.y + d.y);
            }
        }

        // ---- layer 1: acc1[64,128] = A @ We1_e^T (+be1) ----
        float acc1[4][2][4];
#pragma unroll
        for (int mt = 0; mt < 4; mt++)
#pragma unroll
            for (int nt = 0; nt < 2; nt++) {
                acc1[mt][nt][0] = bb1[nt].x; acc1[mt][nt][1] = bb1[nt].y;
                acc1[mt][nt][2] = bb1[nt].x; acc1[mt][nt][3] = bb1[nt].y;
            }
#pragma unroll
        for (int mt = 0; mt < 4; mt++) {
            const u32 bh = ahb + offA + mt * (16 * SA_STRIDE * 2);
            const u32 bl = alb + offA + mt * (16 * SA_STRIDE * 2);
#pragma unroll
            for (int kt = 0; kt < 4; kt++) {
                u32 ah[4], al[4];
                ldsm4(ah, bh + kt * 32);
                ldsm4(al, bl + kt * 32);
#pragma unroll
                for (int nt = 0; nt < 2; nt++) {
                    mma_bf(acc1[mt][nt], ah, b1h[nt][kt]);
                    mma_bf(acc1[mt][nt], ah, b1l[nt][kt]);
                    mma_bf(acc1[mt][nt], al, b1h[nt][kt]);
                }
            }
        }

        // ---- epilogue1: h = relu(acc1 + psum) -> H smem bf16 hi/lo ----
#pragma unroll
        for (int nt = 0; nt < 2; nt++) {
            const int n0 = wid * 16 + nt * 8 + cq;
#pragma unroll
            for (int mt = 0; mt < 4; mt++) {
                const int m0 = mt * 16 + nrow, m1 = m0 + 8;
                const float x0 = fmaxf(acc1[mt][nt][0] + psum[nt][mt][0].x, 0.f);
                const float x1 = fmaxf(acc1[mt][nt][1] + psum[nt][mt][0].y, 0.f);
                const float x2 = fmaxf(acc1[mt][nt][2] + psum[nt][mt][1].x, 0.f);
                const float x3 = fmaxf(acc1[mt][nt][3] + psum[nt][mt][1].y, 0.f);
                const u32 h0 = pack_bf2(x0, x1);
                const u32 h1 = pack_bf2(x2, x3);
                *(u32*)(sm + EOFF_HH + (m0 * SH_STRIDE + n0) * 2) = h0;
                *(u32*)(sm + EOFF_HH + (m1 * SH_STRIDE + n0) * 2) = h1;
                *(u32*)(sm + EOFF_HL + (m0 * SH_STRIDE + n0) * 2) =
                    pack_bf2(x0 - lowf(h0), x1 - highf(h0));
                *(u32*)(sm + EOFF_HL + (m1 * SH_STRIDE + n0) * 2) =
                    pack_bf2(x2 - lowf(h1), x3 - highf(h1));
            }
        }
        __syncthreads();

        // ---- layer 2: acc2[64,64] = h @ We2^T (+be2); B frags via ldmatrix ----
        float acc2[4][4];
#pragma unroll
        for (int mt = 0; mt < 4; mt++) {
            acc2[mt][0] = bb2.x; acc2[mt][1] = bb2.y;
            acc2[mt][2] = bb2.x; acc2[mt][3] = bb2.y;
        }
#pragma unroll
        for (int kt = 0; kt < 8; kt++) {
            u32 bfh[2], bfl[2];
            ldsm2(bfh, w2h + offB + kt * 32);
            ldsm2(bfl, w2l + offB + kt * 32);
#pragma unroll
            for (int mt = 0; mt < 4; mt++) {
                u32 ah[4], al[4];
                const u32 rb = mt * (16 * SH_STRIDE * 2) + kt * 32;
                ldsm4(ah, hhb + offH + rb);
                ldsm4(al, hlb + offH + rb);
                mma_bf(acc2[mt], ah, bfh);
                mma_bf(acc2[mt], ah, bfl);
                mma_bf(acc2[mt], al, bfh);
            }
        }

        // ---- epilogue2: stage fp32 -> float4 stores + atomics ----
        {
            const int n2 = wid * 8 + cq;
#pragma unroll
            for (int mt = 0; mt < 4; mt++) {
                const int m0 = mt * 16 + nrow, m1 = m0 + 8;
                *(float2*)(sF + m0 * 68 + n2) = make_float2(acc2[mt][0], acc2[mt][1]);
                *(float2*)(sF + m1 * 68 + n2) = make_float2(acc2[mt][2], acc2[mt][3]);
            }
        }
        __syncthreads();
        {
            const int row = tid >> 2, q = tid & 3;
            const int ge = base + row;
            if (ge < E) {
                const int ridx = sSR[row];
#pragma unroll
                for (int j = 0; j < 4; j++) {
                    const int col = (q + 4 * j) * 4;
                    const float4 v = *(const float4*)(sF + row * 68 + col);
                    *(float4*)(e_out + (size_t)ge * 64 + col) = v;
                    atomicAdd((float4*)(g_agg + (size_t)ridx * 64 + col), v);
                }
            }
        }
    }
}

// ============================================================================
// Node kernel (round-5 proven shape): 512 threads, 128-row tiles, 1 CTA/SM.
// n = relu(agg@Wn1_a + Q[node] + bn1) @ Wn2 + bn2
__global__ __launch_bounds__(512, 1)
void node_kernel(const float* __restrict__ Wn1, const float* __restrict__ bn1,
                 const float* __restrict__ Wn2, const float* __restrict__ bn2,
                 float* __restrict__ n_out, int N)
{
    char* sm = smem_raw;
    const u32 smb = smem_u32(sm);
    const u32 ahb = smb + BOFF_AH, alb = smb + BOFF_AL;
    const u32 hhb = smb + BOFF_HH, hlb = smb + BOFF_HL;

    const int tid = threadIdx.x, wid = tid >> 5, lid = tid & 31;
    const int nrow = lid >> 2, cq = (lid & 3) * 2;
    const int mh = wid >> 3;
    const int base = blockIdx.x * 128;

    u32 b1h[4][2], b1l[4][2];
    {
        const int n = wid * 8 + nrow;
#pragma unroll
        for (int kt = 0; kt < 4; kt++)
#pragma unroll
            for (int r = 0; r < 2; r++)
                build_frag(Wn1, 128, n, kt * 16 + cq + r * 8, b1h[kt][r], b1l[kt][r]);
    }
    u32 b2h[8][2], b2l[8][2];
    {
        const int n = (wid & 7) * 8 + nrow;
#pragma unroll
        for (int kt = 0; kt < 8; kt++)
#pragma unroll
            for (int r = 0; r < 2; r++)
                build_frag(Wn2, 64, n, kt * 16 + cq + r * 8, b2h[kt][r], b2l[kt][r]);
    }
    const float2 bb1 = *(const float2*)(bn1 + wid * 8 + cq);
    const float2 bb2 = *(const float2*)(bn2 + (wid & 7) * 8 + cq);

    const int trow = (lid & 7) + ((lid >> 3) & 1) * 8;
    const int tcol = (lid >> 4) * 8;
    const u32 offA = (u32)(trow * SA_STRIDE + tcol) * 2;
    const u32 offH = (u32)(trow * SH_STRIDE + tcol) * 2;

    {
        const int row = tid >> 2, q = tid & 3;
        int g = base + row; if (g >= N) g = N - 1;
        stage_row_quarter(sm, (const float4*)(g_agg + (size_t)g * 64), row, q, BOFF_AH, BOFF_AL);
    }
    __syncthreads();

    float acc1[8][4];
#pragma unroll
    for (int mt = 0; mt < 8; mt++) {
        acc1[mt][0] = bb1.x; acc1[mt][1] = bb1.y;
        acc1[mt][2] = bb1.x; acc1[mt][3] = bb1.y;
    }
#pragma unroll
    for (int mt = 0; mt < 8; mt++) {
        const u32 bh = ahb + offA + mt * (16 * SA_STRIDE * 2);
        const u32 bl = alb + offA + mt * (16 * SA_STRIDE * 2);
#pragma unroll
        for (int kt = 0; kt < 4; kt++) {
            u32 ah[4], al[4];
            ldsm4(ah, bh + kt * 32);
            ldsm4(al, bl + kt * 32);
            mma_bf(acc1[mt], ah, b1h[kt]);
            mma_bf(acc1[mt], ah, b1l[kt]);
            mma_bf(acc1[mt], al, b1h[kt]);
        }
    }

    {
        const int n0 = wid * 8 + cq;
#pragma unroll
        for (int mt = 0; mt < 8; mt++) {
            const int m0 = mt * 16 + nrow, m1 = m0 + 8;
            int g0 = base + m0; if (g0 >= N) g0 = N - 1;
            int g1 = base + m1; if (g1 >= N) g1 = N - 1;
            const float2 qa = __ldg((const float2*)(g_P + (size_t)g0 * 384 + 256 + n0));
            const float2 qb = __ldg((const float2*)(g_P + (size_t)g1 * 384 + 256 + n0));
            const float x0 = fmaxf(acc1[mt][0] + qa.x, 0.f);
            const float x1 = fmaxf(acc1[mt][1] + qa.y, 0.f);
            const float x2 = fmaxf(acc1[mt][2] + qb.x, 0.f);
            const float x3 = fmaxf(acc1[mt][3] + qb.y, 0.f);
            const u32 h0 = pack_bf2(x0, x1);
            const u32 h1 = pack_bf2(x2, x3);
            *(u32*)(sm + BOFF_HH + (m0 * SH_STRIDE + n0) * 2) = h0;
            *(u32*)(sm + BOFF_HH + (m1 * SH_STRIDE + n0) * 2) = h1;
            *(u32*)(sm + BOFF_HL + (m0 * SH_STRIDE + n0) * 2) =
                pack_bf2(x0 - lowf(h0), x1 - highf(h0));
            *(u32*)(sm + BOFF_HL + (m1 * SH_STRIDE + n0) * 2) =
                pack_bf2(x2 - lowf(h1), x3 - highf(h1));
        }
    }
    __syncthreads();

    float acc2[4][4];
#pragma unroll
    for (int mt = 0; mt < 4; mt++) {
        acc2[mt][0] = bb2.x; acc2[mt][1] = bb2.y;
        acc2[mt][2] = bb2.x; acc2[mt][3] = bb2.y;
    }
#pragma unroll
    for (int mt = 0; mt < 4; mt++) {
        const int rowbase = (mh * 4 + mt) * 16;
        const u32 bh = hhb + offH + rowbase * (SH_STRIDE * 2);
        const u32 bl = hlb + offH + rowbase * (SH_STRIDE * 2);
#pragma unroll
        for (int kt = 0; kt < 8; kt++) {
            u32 ah[4], al[4];
            ldsm4(ah, bh + kt * 32);
            ldsm4(al, bl + kt * 32);
            mma_bf(acc2[mt], ah, b2h[kt]);
            mma_bf(acc2[mt], ah, b2l[kt]);
            mma_bf(acc2[mt], al, b2h[kt]);
        }
    }

    {
        const int n2 = (wid & 7) * 8 + cq;
#pragma unroll
        for (int mt = 0; mt < 4; mt++) {
            const int m0 = mh * 64 + mt * 16 + nrow, m1 = m0 + 8;
            const int g0 = base + m0, g1 = base + m1;
            if (g0 < N) *(float2*)(n_out + (size_t)g0 * 64 + n2) =
                            make_float2(acc2[mt][0], acc2[mt][1]);
            if (g1 < N) *(float2*)(n_out + (size_t)g1 * 64 + n2) =
                            make_float2(acc2[mt][2], acc2[mt][3]);
        }
    }
}

// ============================================================================
extern "C" void kernel_launch(void* const* d_in, const int* in_sizes, int n_in,
                              void* d_out, int out_size)
{
    const float* node_feats = (const float*)d_in[0];
    const float* edge_feats = (const float*)d_in[1];
    const float* We1 = (const float*)d_in[2];
    const float* be1 = (const float*)d_in[3];
    const float* We2 = (const float*)d_in[4];
    const float* be2 = (const float*)d_in[5];
    const float* Wn1 = (const float*)d_in[6];
    const float* bn1 = (const float*)d_in[7];
    const float* Wn2 = (const float*)d_in[8];
    const float* bn2 = (const float*)d_in[9];
    const int* senders   = (const int*)d_in[10];
    const int* receivers = (const int*)d_in[11];

    const int N = in_sizes[0] / D;
    const int E = in_sizes[1] / D;

    float* out   = (float*)d_out;
    float* e_out = out;                   // [E, D]
    float* n_out = out + (size_t)E * D;   // [N, D]

    cudaFuncSetAttribute(pproj_kernel, cudaFuncAttributeMaxDynamicSharedMemorySize, PPROJ_SMEM);
    cudaFuncSetAttribute(edge_kernel,  cudaFuncAttributeMaxDynamicSharedMemorySize, EDGE_SMEM);
    cudaFuncSetAttribute(node_kernel,  cudaFuncAttributeMaxDynamicSharedMemorySize, BIG_SMEM);

    int dev = 0, sms = 148;
    cudaGetDevice(&dev);
    cudaDeviceGetAttribute(&sms, cudaDevAttrMultiProcessorCount, dev);

    const int n4 = N * D / 4;
    zero_agg_kernel<<<(n4 + 255) / 256, 256>>>(n4);

    pproj_kernel<<<(N + 127) / 128, 512, PPROJ_SMEM>>>(node_feats, We1, Wn1, N);

    edge_kernel<<<2 * sms, 256, EDGE_SMEM>>>(edge_feats, We1, be1, We2, be2,
                                             senders, receivers, e_out, E);

    node_kernel<<<(N + 127) / 128, 512, BIG_SMEM>>>(Wn1, bn1, Wn2, bn2, n_out, N);
}